// round 3
// baseline (speedup 1.0000x reference)
#include <cuda_runtime.h>

#define BSZ 8
#define NH 16
#define SEQL 1024
#define DM 1024
#define DK 64

// Scratch (static device globals -- no allocation)
static __device__ float g_qh [(size_t)BSZ*NH*SEQL*DK];   // 33.5 MB
static __device__ float g_kh [(size_t)BSZ*NH*SEQL*DK];
static __device__ float g_vh [(size_t)BSZ*NH*SEQL*DK];
static __device__ float g_sc [(size_t)BSZ*NH*SEQL*SEQL]; // 537 MB
static __device__ float g_ctx[(size_t)BSZ*NH*SEQL*DK];

// ---------------------------------------------------------------------------
// Projection GEMM: Out(head layout [b,h,s,dk]) = X[8192,1024] @ W[1024,1024] + b
// 128x128x8 tile, 256 threads, 8x8 per thread.
// sel: 0 -> g_qh, 1 -> g_kh, 2 -> g_vh
// ---------------------------------------------------------------------------
__global__ __launch_bounds__(256) void proj_kernel(
    const float* __restrict__ X, const float* __restrict__ W,
    const float* __restrict__ bias, int sel)
{
    float* __restrict__ Out = (sel == 0) ? g_qh : (sel == 1) ? g_kh : g_vh;

    __shared__ float As[8][128];
    __shared__ float Bs[8][128];

    const int tid  = threadIdx.x;
    const int m0   = blockIdx.y * 128;
    const int n0   = blockIdx.x * 128;
    const int arow = tid >> 1,  ac4 = (tid & 1) * 4;
    const int brow = tid >> 5,  bc4 = (tid & 31) * 4;
    const int tx   = tid & 15,  ty  = tid >> 4;

    float acc[8][8];
#pragma unroll
    for (int i = 0; i < 8; i++)
#pragma unroll
        for (int j = 0; j < 8; j++) acc[i][j] = 0.f;

    for (int k0 = 0; k0 < DM; k0 += 8) {
        float4 a = *(const float4*)&X[(size_t)(m0 + arow) * DM + k0 + ac4];
        As[ac4 + 0][arow] = a.x;
        As[ac4 + 1][arow] = a.y;
        As[ac4 + 2][arow] = a.z;
        As[ac4 + 3][arow] = a.w;
        *(float4*)&Bs[brow][bc4] =
            *(const float4*)&W[(size_t)(k0 + brow) * DM + n0 + bc4];
        __syncthreads();
#pragma unroll
        for (int k = 0; k < 8; k++) {
            float4 a0 = *(const float4*)&As[k][ty * 8];
            float4 a1 = *(const float4*)&As[k][ty * 8 + 4];
            float4 b0 = *(const float4*)&Bs[k][tx * 8];
            float4 b1 = *(const float4*)&Bs[k][tx * 8 + 4];
            float av[8] = {a0.x, a0.y, a0.z, a0.w, a1.x, a1.y, a1.z, a1.w};
            float bv[8] = {b0.x, b0.y, b0.z, b0.w, b1.x, b1.y, b1.z, b1.w};
#pragma unroll
            for (int i = 0; i < 8; i++)
#pragma unroll
                for (int j = 0; j < 8; j++) acc[i][j] += av[i] * bv[j];
        }
        __syncthreads();
    }

    // bias (depends only on n)
    float4 bb0 = *(const float4*)&bias[n0 + tx * 8];
    float4 bb1 = *(const float4*)&bias[n0 + tx * 8 + 4];
    float bbv[8] = {bb0.x, bb0.y, bb0.z, bb0.w, bb1.x, bb1.y, bb1.z, bb1.w};

#pragma unroll
    for (int i = 0; i < 8; i++) {
        int m = m0 + ty * 8 + i;
        int b = m >> 10, s = m & 1023;
#pragma unroll
        for (int jj = 0; jj < 2; jj++) {
            int n = n0 + tx * 8 + jj * 4;
            int h = n >> 6, dk = n & 63;
            float4 o;
            o.x = acc[i][jj * 4 + 0] + bbv[jj * 4 + 0];
            o.y = acc[i][jj * 4 + 1] + bbv[jj * 4 + 1];
            o.z = acc[i][jj * 4 + 2] + bbv[jj * 4 + 2];
            o.w = acc[i][jj * 4 + 3] + bbv[jj * 4 + 3];
            *(float4*)&Out[(((size_t)b * NH + h) * SEQL + s) * DK + dk] = o;
        }
    }
}

// ---------------------------------------------------------------------------
// Scores: per (b,h): S[1024,1024] = (Qh @ Kh^T) * 0.125, mask==0 -> -1e9
// ---------------------------------------------------------------------------
__global__ __launch_bounds__(256) void scores_kernel(const int* __restrict__ mask)
{
    const int z = blockIdx.z;         // b*NH + h
    const int b = z >> 4;
    const float* __restrict__ Q  = g_qh + (size_t)z * SEQL * DK;
    const float* __restrict__ Kh = g_kh + (size_t)z * SEQL * DK;
    float* __restrict__ S = g_sc + (size_t)z * SEQL * SEQL;
    const int* __restrict__ M = mask + (size_t)b * SEQL * SEQL;

    __shared__ float As[8][128];
    __shared__ float Bs[8][128];

    const int tid  = threadIdx.x;
    const int m0   = blockIdx.y * 128;
    const int n0   = blockIdx.x * 128;
    const int arow = tid >> 1, ac4 = (tid & 1) * 4;
    const int tx   = tid & 15, ty  = tid >> 4;

    float acc[8][8];
#pragma unroll
    for (int i = 0; i < 8; i++)
#pragma unroll
        for (int j = 0; j < 8; j++) acc[i][j] = 0.f;

    for (int k0 = 0; k0 < DK; k0 += 8) {
        float4 a = *(const float4*)&Q[(size_t)(m0 + arow) * DK + k0 + ac4];
        As[ac4 + 0][arow] = a.x;
        As[ac4 + 1][arow] = a.y;
        As[ac4 + 2][arow] = a.z;
        As[ac4 + 3][arow] = a.w;
        float4 kv = *(const float4*)&Kh[(size_t)(n0 + arow) * DK + k0 + ac4];
        Bs[ac4 + 0][arow] = kv.x;
        Bs[ac4 + 1][arow] = kv.y;
        Bs[ac4 + 2][arow] = kv.z;
        Bs[ac4 + 3][arow] = kv.w;
        __syncthreads();
#pragma unroll
        for (int k = 0; k < 8; k++) {
            float4 a0 = *(const float4*)&As[k][ty * 8];
            float4 a1 = *(const float4*)&As[k][ty * 8 + 4];
            float4 b0 = *(const float4*)&Bs[k][tx * 8];
            float4 b1 = *(const float4*)&Bs[k][tx * 8 + 4];
            float av[8] = {a0.x, a0.y, a0.z, a0.w, a1.x, a1.y, a1.z, a1.w};
            float bv[8] = {b0.x, b0.y, b0.z, b0.w, b1.x, b1.y, b1.z, b1.w};
#pragma unroll
            for (int i = 0; i < 8; i++)
#pragma unroll
                for (int j = 0; j < 8; j++) acc[i][j] += av[i] * bv[j];
        }
        __syncthreads();
    }

#pragma unroll
    for (int i = 0; i < 8; i++) {
        int m = m0 + ty * 8 + i;
#pragma unroll
        for (int jj = 0; jj < 2; jj++) {
            int n = n0 + tx * 8 + jj * 4;
            int4 mk = *(const int4*)&M[(size_t)m * SEQL + n];
            float4 o;
            o.x = mk.x ? acc[i][jj * 4 + 0] * 0.125f : -1e9f;
            o.y = mk.y ? acc[i][jj * 4 + 1] * 0.125f : -1e9f;
            o.z = mk.z ? acc[i][jj * 4 + 2] * 0.125f : -1e9f;
            o.w = mk.w ? acc[i][jj * 4 + 3] * 0.125f : -1e9f;
            *(float4*)&S[(size_t)m * SEQL + n] = o;
        }
    }
}

// ---------------------------------------------------------------------------
// Softmax over last dim (1024), in place on g_sc. One block per row.
// ---------------------------------------------------------------------------
__global__ __launch_bounds__(256) void softmax_kernel()
{
    const size_t row = blockIdx.x;
    float4* __restrict__ p = (float4*)(g_sc + row * SEQL);
    const int tid = threadIdx.x;

    float4 v = p[tid];
    float mx = fmaxf(fmaxf(v.x, v.y), fmaxf(v.z, v.w));
#pragma unroll
    for (int o = 16; o; o >>= 1) mx = fmaxf(mx, __shfl_xor_sync(0xffffffffu, mx, o));

    __shared__ float smax[8];
    __shared__ float ssum[8];
    if ((tid & 31) == 0) smax[tid >> 5] = mx;
    __syncthreads();
    mx = smax[0];
#pragma unroll
    for (int w = 1; w < 8; w++) mx = fmaxf(mx, smax[w]);

    float e0 = __expf(v.x - mx), e1 = __expf(v.y - mx);
    float e2 = __expf(v.z - mx), e3 = __expf(v.w - mx);
    float s = e0 + e1 + e2 + e3;
#pragma unroll
    for (int o = 16; o; o >>= 1) s += __shfl_xor_sync(0xffffffffu, s, o);
    if ((tid & 31) == 0) ssum[tid >> 5] = s;
    __syncthreads();
    s = ssum[0];
#pragma unroll
    for (int w = 1; w < 8; w++) s += ssum[w];

    float inv = 1.f / s;
    v.x = e0 * inv; v.y = e1 * inv; v.z = e2 * inv; v.w = e3 * inv;
    p[tid] = v;
}

// ---------------------------------------------------------------------------
// Context: per (b,h): C[1024,64] = P[1024,1024] @ Vh[1024,64]
// BM=128, BN=64, BK=8, 256 threads, 8x4 per thread.
// ---------------------------------------------------------------------------
__global__ __launch_bounds__(256) void ctx_kernel()
{
    const int z = blockIdx.z;
    const float* __restrict__ P = g_sc  + (size_t)z * SEQL * SEQL;
    const float* __restrict__ V = g_vh  + (size_t)z * SEQL * DK;
    float* __restrict__ C       = g_ctx + (size_t)z * SEQL * DK;

    __shared__ float As[8][128];
    __shared__ float Bs[8][64];

    const int tid  = threadIdx.x;
    const int m0   = blockIdx.y * 128;
    const int arow = tid >> 1, ac4 = (tid & 1) * 4;
    const int brow = tid >> 5, bc2 = (tid & 31) * 2;
    const int tx   = tid & 15, ty  = tid >> 4;   // tx: 16*4=64 cols, ty: 16*8=128 rows

    float acc[8][4];
#pragma unroll
    for (int i = 0; i < 8; i++)
#pragma unroll
        for (int j = 0; j < 4; j++) acc[i][j] = 0.f;

    for (int k0 = 0; k0 < SEQL; k0 += 8) {
        float4 a = *(const float4*)&P[(size_t)(m0 + arow) * SEQL + k0 + ac4];
        As[ac4 + 0][arow] = a.x;
        As[ac4 + 1][arow] = a.y;
        As[ac4 + 2][arow] = a.z;
        As[ac4 + 3][arow] = a.w;
        *(float2*)&Bs[brow][bc2] =
            *(const float2*)&V[(size_t)(k0 + brow) * DK + bc2];
        __syncthreads();
#pragma unroll
        for (int k = 0; k < 8; k++) {
            float4 a0 = *(const float4*)&As[k][ty * 8];
            float4 a1 = *(const float4*)&As[k][ty * 8 + 4];
            float4 b0 = *(const float4*)&Bs[k][tx * 4];
            float av[8] = {a0.x, a0.y, a0.z, a0.w, a1.x, a1.y, a1.z, a1.w};
            float bv[4] = {b0.x, b0.y, b0.z, b0.w};
#pragma unroll
            for (int i = 0; i < 8; i++)
#pragma unroll
                for (int j = 0; j < 4; j++) acc[i][j] += av[i] * bv[j];
        }
        __syncthreads();
    }

#pragma unroll
    for (int i = 0; i < 8; i++) {
        int m = m0 + ty * 8 + i;
        float4 o = make_float4(acc[i][0], acc[i][1], acc[i][2], acc[i][3]);
        *(float4*)&C[((size_t)m) * DK + tx * 4] = o;
    }
}

// ---------------------------------------------------------------------------
// Output projection: out[8192,1024] = concat(g_ctx) @ Wo + bo
// A is gathered from head layout on the fly.
// ---------------------------------------------------------------------------
__global__ __launch_bounds__(256) void out_kernel(
    const float* __restrict__ Wo, const float* __restrict__ bo,
    float* __restrict__ Out)
{
    __shared__ float As[8][128];
    __shared__ float Bs[8][128];

    const int tid  = threadIdx.x;
    const int m0   = blockIdx.y * 128;
    const int n0   = blockIdx.x * 128;
    const int arow = tid >> 1,  ac4 = (tid & 1) * 4;
    const int brow = tid >> 5,  bc4 = (tid & 31) * 4;
    const int tx   = tid & 15,  ty  = tid >> 4;

    const int m = m0 + arow;
    const int b = m >> 10, s = m & 1023;

    float acc[8][8];
#pragma unroll
    for (int i = 0; i < 8; i++)
#pragma unroll
        for (int j = 0; j < 8; j++) acc[i][j] = 0.f;

    for (int k0 = 0; k0 < DM; k0 += 8) {
        int kk = k0 + ac4;
        int h = kk >> 6, dk = kk & 63;
        float4 a = *(const float4*)&g_ctx[(((size_t)b * NH + h) * SEQL + s) * DK + dk];
        As[ac4 + 0][arow] = a.x;
        As[ac4 + 1][arow] = a.y;
        As[ac4 + 2][arow] = a.z;
        As[ac4 + 3][arow] = a.w;
        *(float4*)&Bs[brow][bc4] =
            *(const float4*)&Wo[(size_t)(k0 + brow) * DM + n0 + bc4];
        __syncthreads();
#pragma unroll
        for (int k = 0; k < 8; k++) {
            float4 a0 = *(const float4*)&As[k][ty * 8];
            float4 a1 = *(const float4*)&As[k][ty * 8 + 4];
            float4 b0 = *(const float4*)&Bs[k][tx * 8];
            float4 b1 = *(const float4*)&Bs[k][tx * 8 + 4];
            float av[8] = {a0.x, a0.y, a0.z, a0.w, a1.x, a1.y, a1.z, a1.w};
            float bv[8] = {b0.x, b0.y, b0.z, b0.w, b1.x, b1.y, b1.z, b1.w};
#pragma unroll
            for (int i = 0; i < 8; i++)
#pragma unroll
                for (int j = 0; j < 8; j++) acc[i][j] += av[i] * bv[j];
        }
        __syncthreads();
    }

    float4 bb0 = *(const float4*)&bo[n0 + tx * 8];
    float4 bb1 = *(const float4*)&bo[n0 + tx * 8 + 4];
    float bbv[8] = {bb0.x, bb0.y, bb0.z, bb0.w, bb1.x, bb1.y, bb1.z, bb1.w};

#pragma unroll
    for (int i = 0; i < 8; i++) {
        int mm = m0 + ty * 8 + i;
#pragma unroll
        for (int jj = 0; jj < 2; jj++) {
            int n = n0 + tx * 8 + jj * 4;
            float4 o;
            o.x = acc[i][jj * 4 + 0] + bbv[jj * 4 + 0];
            o.y = acc[i][jj * 4 + 1] + bbv[jj * 4 + 1];
            o.z = acc[i][jj * 4 + 2] + bbv[jj * 4 + 2];
            o.w = acc[i][jj * 4 + 3] + bbv[jj * 4 + 3];
            *(float4*)&Out[(size_t)mm * DM + n] = o;
        }
    }
}

// ---------------------------------------------------------------------------
extern "C" void kernel_launch(void* const* d_in, const int* in_sizes, int n_in,
                              void* d_out, int out_size)
{
    const float* q    = (const float*)d_in[0];
    const float* k    = (const float*)d_in[1];
    const float* v    = (const float*)d_in[2];
    const int*   mask = (const int*)  d_in[3];
    const float* Wq   = (const float*)d_in[4];
    const float* bq   = (const float*)d_in[5];
    const float* Wk   = (const float*)d_in[6];
    const float* bk   = (const float*)d_in[7];
    const float* Wv   = (const float*)d_in[8];
    const float* bv   = (const float*)d_in[9];
    const float* Wo   = (const float*)d_in[10];
    const float* bo   = (const float*)d_in[11];
    float* out = (float*)d_out;

    dim3 blk(256);
    dim3 gProj(DM / 128, (BSZ * SEQL) / 128);          // (8, 64)
    proj_kernel<<<gProj, blk>>>(q, Wq, bq, 0);
    proj_kernel<<<gProj, blk>>>(k, Wk, bk, 1);
    proj_kernel<<<gProj, blk>>>(v, Wv, bv, 2);

    dim3 gSc(SEQL / 128, SEQL / 128, BSZ * NH);        // (8, 8, 128)
    scores_kernel<<<gSc, blk>>>(mask);

    softmax_kernel<<<BSZ * NH * SEQL, 256>>>();        // 131072 rows

    dim3 gCtx(1, SEQL / 128, BSZ * NH);                // (1, 8, 128)
    ctx_kernel<<<gCtx, blk>>>();

    dim3 gOut(DM / 128, (BSZ * SEQL) / 128);           // (8, 64)
    out_kernel<<<gOut, blk>>>(Wo, bo, out);
}

// round 5
// speedup vs baseline: 1.4784x; 1.4784x over previous
#include <cuda_runtime.h>
#include <cuda_bf16.h>
#include <cstdint>

#define BSZ 8
#define NH 16
#define SEQL 1024
#define DM 1024
#define DK 64

// fp32 scratch
static __device__ float g_qh [(size_t)BSZ*NH*SEQL*DK];
static __device__ float g_kh [(size_t)BSZ*NH*SEQL*DK];
static __device__ float g_vh [(size_t)BSZ*NH*SEQL*DK];
static __device__ float g_sc [(size_t)BSZ*NH*SEQL*SEQL];
static __device__ float g_ctx[(size_t)BSZ*NH*SEQL*DK];

// bf16 split scratch (reused across the 4 GEMMs)
static __device__ __align__(16) __nv_bfloat16 g_ah[(size_t)BSZ*SEQL*DM];  // A hi [8192][1024]
static __device__ __align__(16) __nv_bfloat16 g_al[(size_t)BSZ*SEQL*DM];  // A lo
static __device__ __align__(16) __nv_bfloat16 g_bh[(size_t)DM*DM];        // W^T hi [N][K]
static __device__ __align__(16) __nv_bfloat16 g_bl[(size_t)DM*DM];        // W^T lo

// ===========================================================================
// helpers
// ===========================================================================
__device__ __forceinline__ uint32_t smem_u32(const void* p) {
    uint32_t a;
    asm("{ .reg .u64 t; cvta.to.shared.u64 t, %1; cvt.u32.u64 %0, t; }" : "=r"(a) : "l"(p));
    return a;
}

#define LDMX4(r0, r1, r2, r3, addr) \
    asm volatile("ldmatrix.sync.aligned.m8n8.x4.shared.b16 {%0,%1,%2,%3}, [%4];" \
        : "=r"(r0), "=r"(r1), "=r"(r2), "=r"(r3) : "r"(addr))

#define MMA16816(c, a, b0, b1) \
    asm volatile("mma.sync.aligned.m16n8k16.row.col.f32.bf16.bf16.f32 " \
        "{%0,%1,%2,%3}, {%4,%5,%6,%7}, {%8,%9}, {%0,%1,%2,%3};" \
        : "+f"((c)[0]), "+f"((c)[1]), "+f"((c)[2]), "+f"((c)[3]) \
        : "r"((a)[0]), "r"((a)[1]), "r"((a)[2]), "r"((a)[3]), "r"(b0), "r"(b1))

__device__ __forceinline__ void split2(float x, float y,
                                       uint32_t& hi, uint32_t& lo) {
    __nv_bfloat16 hx = __float2bfloat16_rn(x);
    __nv_bfloat16 hy = __float2bfloat16_rn(y);
    __nv_bfloat162 hp(hx, hy);
    __nv_bfloat162 lp = __floats2bfloat162_rn(x - __bfloat162float(hx),
                                              y - __bfloat162float(hy));
    hi = *(uint32_t*)&hp;
    lo = *(uint32_t*)&lp;
}

// ===========================================================================
// Elementwise split: src fp32 [n] -> g_ah, g_al bf16 (same layout)
// ===========================================================================
__global__ __launch_bounds__(256) void split_input_kernel(const float* __restrict__ src)
{
    const size_t i4 = (size_t)blockIdx.x * 256 + threadIdx.x;   // one float4
    float4 x = *(const float4*)(src + i4 * 4);
    uint32_t h0, l0, h1, l1;
    split2(x.x, x.y, h0, l0);
    split2(x.z, x.w, h1, l1);
    *(uint2*)(g_ah + i4 * 4) = make_uint2(h0, h1);
    *(uint2*)(g_al + i4 * 4) = make_uint2(l0, l1);
}

// ===========================================================================
// Gather ctx (head layout) -> plain [m][k] bf16 split
// ===========================================================================
__global__ __launch_bounds__(256) void ctx_split_kernel()
{
    const size_t i4 = (size_t)blockIdx.x * 256 + threadIdx.x;
    const size_t p  = i4 * 4;
    const int m = (int)(p >> 10), k = (int)(p & 1023);
    const int b = m >> 10, s = m & 1023, h = k >> 6, dk = k & 63;
    float4 x = *(const float4*)&g_ctx[(((size_t)b * NH + h) * SEQL + s) * DK + dk];
    uint32_t h0, l0, h1, l1;
    split2(x.x, x.y, h0, l0);
    split2(x.z, x.w, h1, l1);
    *(uint2*)(g_ah + p) = make_uint2(h0, h1);
    *(uint2*)(g_al + p) = make_uint2(l0, l1);
}

// ===========================================================================
// Weight transpose + split: W[k][n] -> g_bh/g_bl [n][k] bf16
// ===========================================================================
__global__ __launch_bounds__(256) void transpose_split_kernel(const float* __restrict__ W)
{
    __shared__ float t[32][33];
    const int bx = blockIdx.x * 32, by = blockIdx.y * 32;
    const int tx = threadIdx.x, ty = threadIdx.y;  // 32x8
#pragma unroll
    for (int j = 0; j < 32; j += 8)
        t[ty + j][tx] = W[(size_t)(by + ty + j) * DM + bx + tx];
    __syncthreads();
#pragma unroll
    for (int j = 0; j < 32; j += 8) {
        float x = t[tx][ty + j];
        __nv_bfloat16 h = __float2bfloat16_rn(x);
        __nv_bfloat16 l = __float2bfloat16_rn(x - __bfloat162float(h));
        const size_t o = (size_t)(bx + ty + j) * DM + by + tx;
        g_bh[o] = h;
        g_bl[o] = l;
    }
}

// ===========================================================================
// Tensor-core GEMM via mma.sync bf16 hi/lo split (3 MMAs):
//   C[8192,1024] = A @ B^T + bias,  A = g_ah/g_al, B = g_bh/g_bl [N][K]
// BM=128, BN=128, BK=32, 256 threads, 8 warps (2m x 4n), warp tile 64x32.
// MODE 0: scatter to head layout (sel 0/1/2 -> g_qh/g_kh/g_vh)
// MODE 1: plain store to OutPlain
// ===========================================================================
#define LDA 40   // padded K-stride (elements); row stride 80B, 16B aligned, conflict-free

template <int MODE>
__global__ __launch_bounds__(256) void mma_gemm(
    const float* __restrict__ bias, float* __restrict__ OutPlain, int sel)
{
    __shared__ __nv_bfloat16 sAh[128][LDA];
    __shared__ __nv_bfloat16 sAl[128][LDA];
    __shared__ __nv_bfloat16 sBh[128][LDA];
    __shared__ __nv_bfloat16 sBl[128][LDA];

    const int tid  = threadIdx.x;
    const int wid  = tid >> 5;
    const int lane = tid & 31;
    const int m0 = blockIdx.y * 128;
    const int n0 = blockIdx.x * 128;

    const int base_m = (wid >> 2) * 64;   // 2 warps in m
    const int base_n = (wid & 3) * 32;    // 4 warps in n

    // global load mapping: row = tid>>2 (and +64), chunk = (tid&3)*8 elems
    const int grow = tid >> 2;
    const int gch  = (tid & 3) * 8;

    const uint32_t aHb = smem_u32(sAh), aLb = smem_u32(sAl);
    const uint32_t bHb = smem_u32(sBh), bLb = smem_u32(sBl);

    // ldmatrix per-lane offsets (bytes)
    const uint32_t a_lane = (uint32_t)(((lane & 15) * LDA + (lane >> 4) * 8) * 2);
    const uint32_t b_lane = (uint32_t)(((((lane >> 4) & 1) * 8 + (lane & 7)) * LDA
                                        + ((lane >> 3) & 1) * 8) * 2);

    float c[4][4][4];
#pragma unroll
    for (int i = 0; i < 4; i++)
#pragma unroll
        for (int j = 0; j < 4; j++)
#pragma unroll
            for (int r = 0; r < 4; r++) c[i][j][r] = 0.f;

    for (int kt = 0; kt < DM / 32; kt++) {
        const int k0 = kt * 32;

        // global loads (16B each)
        const size_t aoff0 = (size_t)(m0 + grow) * DM + k0 + gch;
        const size_t aoff1 = (size_t)(m0 + grow + 64) * DM + k0 + gch;
        const size_t boff0 = (size_t)(n0 + grow) * DM + k0 + gch;
        const size_t boff1 = (size_t)(n0 + grow + 64) * DM + k0 + gch;
        uint4 vah0 = *(const uint4*)(g_ah + aoff0);
        uint4 vah1 = *(const uint4*)(g_ah + aoff1);
        uint4 val0 = *(const uint4*)(g_al + aoff0);
        uint4 val1 = *(const uint4*)(g_al + aoff1);
        uint4 vbh0 = *(const uint4*)(g_bh + boff0);
        uint4 vbh1 = *(const uint4*)(g_bh + boff1);
        uint4 vbl0 = *(const uint4*)(g_bl + boff0);
        uint4 vbl1 = *(const uint4*)(g_bl + boff1);

        __syncthreads();   // previous compute done reading smem

        {
            const uint32_t so0 = (uint32_t)(grow * (LDA * 2) + gch * 2);
            const uint32_t so1 = (uint32_t)((grow + 64) * (LDA * 2) + gch * 2);
            *(uint4*)((char*)sAh + so0) = vah0;
            *(uint4*)((char*)sAh + so1) = vah1;
            *(uint4*)((char*)sAl + so0) = val0;
            *(uint4*)((char*)sAl + so1) = val1;
            *(uint4*)((char*)sBh + so0) = vbh0;
            *(uint4*)((char*)sBh + so1) = vbh1;
            *(uint4*)((char*)sBl + so0) = vbl0;
            *(uint4*)((char*)sBl + so1) = vbl1;
        }
        __syncthreads();

#pragma unroll
        for (int ks = 0; ks < 2; ks++) {
            // B fragments: 2 x ldmatrix.x4 per matrix cover 32 n
            uint32_t bh[8], bl[8];
#pragma unroll
            for (int ni2 = 0; ni2 < 2; ni2++) {
                const uint32_t bo = (uint32_t)((base_n + ni2 * 16) * (LDA * 2) + ks * 32) + b_lane;
                LDMX4(bh[ni2 * 4 + 0], bh[ni2 * 4 + 1], bh[ni2 * 4 + 2], bh[ni2 * 4 + 3], bHb + bo);
                LDMX4(bl[ni2 * 4 + 0], bl[ni2 * 4 + 1], bl[ni2 * 4 + 2], bl[ni2 * 4 + 3], bLb + bo);
            }
#pragma unroll
            for (int mi = 0; mi < 4; mi++) {
                const uint32_t ao = (uint32_t)((base_m + mi * 16) * (LDA * 2) + ks * 32) + a_lane;
                uint32_t ah[4], al[4];
                LDMX4(ah[0], ah[1], ah[2], ah[3], aHb + ao);
                LDMX4(al[0], al[1], al[2], al[3], aLb + ao);
#pragma unroll
                for (int ni = 0; ni < 4; ni++) {
                    const int bi = (ni >> 1) * 4 + (ni & 1) * 2;
                    MMA16816(c[mi][ni], ah, bh[bi], bh[bi + 1]);
                    MMA16816(c[mi][ni], ah, bl[bi], bl[bi + 1]);
                    MMA16816(c[mi][ni], al, bh[bi], bh[bi + 1]);
                }
            }
        }
    }

    // epilogue
    const int lr = lane >> 2;
    const int lc = (lane & 3) * 2;
#pragma unroll
    for (int mi = 0; mi < 4; mi++) {
#pragma unroll
        for (int ni = 0; ni < 4; ni++) {
            const int gm = m0 + base_m + mi * 16 + lr;
            const int gn = n0 + base_n + ni * 8 + lc;
            float2 bv = *(const float2*)(bias + gn);
            float2 o0 = make_float2(c[mi][ni][0] + bv.x, c[mi][ni][1] + bv.y);
            float2 o1 = make_float2(c[mi][ni][2] + bv.x, c[mi][ni][3] + bv.y);
            if (MODE == 0) {
                float* Out = (sel == 0) ? g_qh : (sel == 1) ? g_kh : g_vh;
                const int h = gn >> 6, dk = gn & 63;
                {
                    const int b = gm >> 10, s = gm & 1023;
                    *(float2*)&Out[(((size_t)b * NH + h) * SEQL + s) * DK + dk] = o0;
                }
                {
                    const int m2 = gm + 8;
                    const int b = m2 >> 10, s = m2 & 1023;
                    *(float2*)&Out[(((size_t)b * NH + h) * SEQL + s) * DK + dk] = o1;
                }
            } else {
                *(float2*)&OutPlain[(size_t)gm * DM + gn] = o0;
                *(float2*)&OutPlain[(size_t)(gm + 8) * DM + gn] = o1;
            }
        }
    }
}

// ===========================================================================
// Scores: per (b,h): S = (Qh @ Kh^T) * 0.125, mask==0 -> -1e9   (SIMT fp32)
// ===========================================================================
__global__ __launch_bounds__(256) void scores_kernel(const int* __restrict__ mask)
{
    const int z = blockIdx.z;
    const int b = z >> 4;
    const float* __restrict__ Q  = g_qh + (size_t)z * SEQL * DK;
    const float* __restrict__ Kh = g_kh + (size_t)z * SEQL * DK;
    float* __restrict__ S = g_sc + (size_t)z * SEQL * SEQL;
    const int* __restrict__ M = mask + (size_t)b * SEQL * SEQL;

    __shared__ float As[8][128];
    __shared__ float Bs[8][128];

    const int tid  = threadIdx.x;
    const int m0   = blockIdx.y * 128;
    const int n0   = blockIdx.x * 128;
    const int arow = tid >> 1, ac4 = (tid & 1) * 4;
    const int tx   = tid & 15, ty  = tid >> 4;

    float acc[8][8];
#pragma unroll
    for (int i = 0; i < 8; i++)
#pragma unroll
        for (int j = 0; j < 8; j++) acc[i][j] = 0.f;

    for (int k0 = 0; k0 < DK; k0 += 8) {
        float4 a = *(const float4*)&Q[(size_t)(m0 + arow) * DK + k0 + ac4];
        As[ac4 + 0][arow] = a.x;
        As[ac4 + 1][arow] = a.y;
        As[ac4 + 2][arow] = a.z;
        As[ac4 + 3][arow] = a.w;
        float4 kv = *(const float4*)&Kh[(size_t)(n0 + arow) * DK + k0 + ac4];
        Bs[ac4 + 0][arow] = kv.x;
        Bs[ac4 + 1][arow] = kv.y;
        Bs[ac4 + 2][arow] = kv.z;
        Bs[ac4 + 3][arow] = kv.w;
        __syncthreads();
#pragma unroll
        for (int k = 0; k < 8; k++) {
            float4 a0 = *(const float4*)&As[k][ty * 8];
            float4 a1 = *(const float4*)&As[k][ty * 8 + 4];
            float4 b0 = *(const float4*)&Bs[k][tx * 8];
            float4 b1 = *(const float4*)&Bs[k][tx * 8 + 4];
            float av[8] = {a0.x, a0.y, a0.z, a0.w, a1.x, a1.y, a1.z, a1.w};
            float bv[8] = {b0.x, b0.y, b0.z, b0.w, b1.x, b1.y, b1.z, b1.w};
#pragma unroll
            for (int i = 0; i < 8; i++)
#pragma unroll
                for (int j = 0; j < 8; j++) acc[i][j] += av[i] * bv[j];
        }
        __syncthreads();
    }

#pragma unroll
    for (int i = 0; i < 8; i++) {
        int m = m0 + ty * 8 + i;
#pragma unroll
        for (int jj = 0; jj < 2; jj++) {
            int n = n0 + tx * 8 + jj * 4;
            int4 mk = *(const int4*)&M[(size_t)m * SEQL + n];
            float4 o;
            o.x = mk.x ? acc[i][jj * 4 + 0] * 0.125f : -1e9f;
            o.y = mk.y ? acc[i][jj * 4 + 1] * 0.125f : -1e9f;
            o.z = mk.z ? acc[i][jj * 4 + 2] * 0.125f : -1e9f;
            o.w = mk.w ? acc[i][jj * 4 + 3] * 0.125f : -1e9f;
            *(float4*)&S[(size_t)m * SEQL + n] = o;
        }
    }
}

// ===========================================================================
// Softmax over last dim (1024), in place on g_sc. One block per row.
// ===========================================================================
__global__ __launch_bounds__(256) void softmax_kernel()
{
    const size_t row = blockIdx.x;
    float4* __restrict__ p = (float4*)(g_sc + row * SEQL);
    const int tid = threadIdx.x;

    float4 v = p[tid];
    float mx = fmaxf(fmaxf(v.x, v.y), fmaxf(v.z, v.w));
#pragma unroll
    for (int o = 16; o; o >>= 1) mx = fmaxf(mx, __shfl_xor_sync(0xffffffffu, mx, o));

    __shared__ float smax[8];
    __shared__ float ssum[8];
    if ((tid & 31) == 0) smax[tid >> 5] = mx;
    __syncthreads();
    mx = smax[0];
#pragma unroll
    for (int w = 1; w < 8; w++) mx = fmaxf(mx, smax[w]);

    float e0 = __expf(v.x - mx), e1 = __expf(v.y - mx);
    float e2 = __expf(v.z - mx), e3 = __expf(v.w - mx);
    float s = e0 + e1 + e2 + e3;
#pragma unroll
    for (int o = 16; o; o >>= 1) s += __shfl_xor_sync(0xffffffffu, s, o);
    if ((tid & 31) == 0) ssum[tid >> 5] = s;
    __syncthreads();
    s = ssum[0];
#pragma unroll
    for (int w = 1; w < 8; w++) s += ssum[w];

    float inv = 1.f / s;
    v.x = e0 * inv; v.y = e1 * inv; v.z = e2 * inv; v.w = e3 * inv;
    p[tid] = v;
}

// ===========================================================================
// Context: per (b,h): C[1024,64] = P[1024,1024] @ Vh[1024,64]   (SIMT fp32)
// ===========================================================================
__global__ __launch_bounds__(256) void ctx_kernel()
{
    const int z = blockIdx.z;
    const float* __restrict__ P = g_sc  + (size_t)z * SEQL * SEQL;
    const float* __restrict__ V = g_vh  + (size_t)z * SEQL * DK;
    float* __restrict__ C       = g_ctx + (size_t)z * SEQL * DK;

    __shared__ float As[8][128];
    __shared__ float Bs[8][64];

    const int tid  = threadIdx.x;
    const int m0   = blockIdx.y * 128;
    const int arow = tid >> 1, ac4 = (tid & 1) * 4;
    const int brow = tid >> 5, bc2 = (tid & 31) * 2;
    const int tx   = tid & 15, ty  = tid >> 4;

    float acc[8][4];
#pragma unroll
    for (int i = 0; i < 8; i++)
#pragma unroll
        for (int j = 0; j < 4; j++) acc[i][j] = 0.f;

    for (int k0 = 0; k0 < SEQL; k0 += 8) {
        float4 a = *(const float4*)&P[(size_t)(m0 + arow) * SEQL + k0 + ac4];
        As[ac4 + 0][arow] = a.x;
        As[ac4 + 1][arow] = a.y;
        As[ac4 + 2][arow] = a.z;
        As[ac4 + 3][arow] = a.w;
        *(float2*)&Bs[brow][bc2] =
            *(const float2*)&V[(size_t)(k0 + brow) * DK + bc2];
        __syncthreads();
#pragma unroll
        for (int k = 0; k < 8; k++) {
            float4 a0 = *(const float4*)&As[k][ty * 8];
            float4 a1 = *(const float4*)&As[k][ty * 8 + 4];
            float4 b0 = *(const float4*)&Bs[k][tx * 4];
            float av[8] = {a0.x, a0.y, a0.z, a0.w, a1.x, a1.y, a1.z, a1.w};
            float bv[4] = {b0.x, b0.y, b0.z, b0.w};
#pragma unroll
            for (int i = 0; i < 8; i++)
#pragma unroll
                for (int j = 0; j < 4; j++) acc[i][j] += av[i] * bv[j];
        }
        __syncthreads();
    }

#pragma unroll
    for (int i = 0; i < 8; i++) {
        int m = m0 + ty * 8 + i;
        float4 o = make_float4(acc[i][0], acc[i][1], acc[i][2], acc[i][3]);
        *(float4*)&C[((size_t)m) * DK + tx * 4] = o;
    }
}

// ===========================================================================
extern "C" void kernel_launch(void* const* d_in, const int* in_sizes, int n_in,
                              void* d_out, int out_size)
{
    const float* q    = (const float*)d_in[0];
    const float* k    = (const float*)d_in[1];
    const float* v    = (const float*)d_in[2];
    const int*   mask = (const int*)  d_in[3];
    const float* Wq   = (const float*)d_in[4];
    const float* bq   = (const float*)d_in[5];
    const float* Wk   = (const float*)d_in[6];
    const float* bk   = (const float*)d_in[7];
    const float* Wv   = (const float*)d_in[8];
    const float* bv   = (const float*)d_in[9];
    const float* Wo   = (const float*)d_in[10];
    const float* bo   = (const float*)d_in[11];
    float* out = (float*)d_out;

    dim3 gb(256);
    const int nSplit = (BSZ * SEQL * DM) / 4 / 256;    // 8192 blocks
    dim3 tb(32, 8);
    dim3 tg(DM / 32, DM / 32);
    dim3 gg(DM / 128, (BSZ * SEQL) / 128);             // (8, 64)

    split_input_kernel<<<nSplit, gb>>>(q);
    transpose_split_kernel<<<tg, tb>>>(Wq);
    mma_gemm<0><<<gg, gb>>>(bq, nullptr, 0);

    split_input_kernel<<<nSplit, gb>>>(k);
    transpose_split_kernel<<<tg, tb>>>(Wk);
    mma_gemm<0><<<gg, gb>>>(bk, nullptr, 1);

    split_input_kernel<<<nSplit, gb>>>(v);
    transpose_split_kernel<<<tg, tb>>>(Wv);
    mma_gemm<0><<<gg, gb>>>(bv, nullptr, 2);

    dim3 gSc(SEQL / 128, SEQL / 128, BSZ * NH);        // (8, 8, 128)
    scores_kernel<<<gSc, gb>>>(mask);

    softmax_kernel<<<BSZ * NH * SEQL, 256>>>();

    dim3 gCtx(1, SEQL / 128, BSZ * NH);                // (1, 8, 128)
    ctx_kernel<<<gCtx, gb>>>();

    ctx_split_kernel<<<nSplit, gb>>>();
    transpose_split_kernel<<<tg, tb>>>(Wo);
    mma_gemm<1><<<gg, gb>>>(bo, out, 0);
}

// round 10
// speedup vs baseline: 2.1225x; 1.4356x over previous
#include <cuda_runtime.h>
#include <cuda_bf16.h>
#include <cstdint>

#define BSZ 8
#define NH 16
#define SEQL 1024
#define DM 1024
#define DK 64
#define ZTOT (BSZ*NH)

// ---------------------------------------------------------------------------
// Device scratch (static — no allocation)
// ---------------------------------------------------------------------------
static __device__ float g_sc [(size_t)ZTOT*SEQL*SEQL];                        // fp32 scores
static __device__ __align__(16) __nv_bfloat16 g_ph [(size_t)ZTOT*SEQL*SEQL];  // P hi
static __device__ __align__(16) __nv_bfloat16 g_pl [(size_t)ZTOT*SEQL*SEQL];  // P lo
static __device__ __align__(16) __nv_bfloat16 g_qsh[(size_t)ZTOT*SEQL*DK];
static __device__ __align__(16) __nv_bfloat16 g_qsl[(size_t)ZTOT*SEQL*DK];
static __device__ __align__(16) __nv_bfloat16 g_ksh[(size_t)ZTOT*SEQL*DK];
static __device__ __align__(16) __nv_bfloat16 g_ksl[(size_t)ZTOT*SEQL*DK];
static __device__ __align__(16) __nv_bfloat16 g_vsh[(size_t)ZTOT*SEQL*DK];
static __device__ __align__(16) __nv_bfloat16 g_vsl[(size_t)ZTOT*SEQL*DK];
static __device__ __align__(16) __nv_bfloat16 g_ah [(size_t)BSZ*SEQL*DM];     // A hi (inputs / ctx)
static __device__ __align__(16) __nv_bfloat16 g_al [(size_t)BSZ*SEQL*DM];     // A lo
static __device__ __align__(16) __nv_bfloat16 g_bh [(size_t)DM*DM];           // W^T hi [N][K]
static __device__ __align__(16) __nv_bfloat16 g_bl [(size_t)DM*DM];           // W^T lo

// ---------------------------------------------------------------------------
// helpers
// ---------------------------------------------------------------------------
__device__ __forceinline__ uint32_t smem_u32(const void* p) {
    uint32_t a;
    asm("{ .reg .u64 t; cvta.to.shared.u64 t, %1; cvt.u32.u64 %0, t; }" : "=r"(a) : "l"(p));
    return a;
}

#define LDMX4(r0, r1, r2, r3, addr) \
    asm volatile("ldmatrix.sync.aligned.m8n8.x4.shared.b16 {%0,%1,%2,%3}, [%4];" \
        : "=r"(r0), "=r"(r1), "=r"(r2), "=r"(r3) : "r"(addr))

#define LDMX4T(r0, r1, r2, r3, addr) \
    asm volatile("ldmatrix.sync.aligned.m8n8.x4.trans.shared.b16 {%0,%1,%2,%3}, [%4];" \
        : "=r"(r0), "=r"(r1), "=r"(r2), "=r"(r3) : "r"(addr))

#define MMA16816(c, a, b0, b1) \
    asm volatile("mma.sync.aligned.m16n8k16.row.col.f32.bf16.bf16.f32 " \
        "{%0,%1,%2,%3}, {%4,%5,%6,%7}, {%8,%9}, {%0,%1,%2,%3};" \
        : "+f"((c)[0]), "+f"((c)[1]), "+f"((c)[2]), "+f"((c)[3]) \
        : "r"((a)[0]), "r"((a)[1]), "r"((a)[2]), "r"((a)[3]), "r"(b0), "r"(b1))

#define CP16(saddr, gptr) \
    asm volatile("cp.async.cg.shared.global [%0], [%1], 16;" :: "r"((uint32_t)(saddr)), "l"(gptr))
#define CP_COMMIT() asm volatile("cp.async.commit_group;" ::: "memory")
#define CP_WAIT0()  asm volatile("cp.async.wait_group 0;" ::: "memory")

__device__ __forceinline__ void split2(float x, float y, uint32_t& hi, uint32_t& lo) {
    __nv_bfloat16 hx = __float2bfloat16_rn(x);
    __nv_bfloat16 hy = __float2bfloat16_rn(y);
    __nv_bfloat162 hp(hx, hy);
    __nv_bfloat162 lp = __floats2bfloat162_rn(x - __bfloat162float(hx),
                                              y - __bfloat162float(hy));
    hi = *(uint32_t*)&hp;
    lo = *(uint32_t*)&lp;
}

// ---------------------------------------------------------------------------
// input split: fp32 [n] -> g_ah/g_al bf16
// ---------------------------------------------------------------------------
__global__ __launch_bounds__(256) void split_input_kernel(const float* __restrict__ src)
{
    const size_t i4 = (size_t)blockIdx.x * 256 + threadIdx.x;
    float4 x = *(const float4*)(src + i4 * 4);
    uint32_t h0, l0, h1, l1;
    split2(x.x, x.y, h0, l0);
    split2(x.z, x.w, h1, l1);
    *(uint2*)(g_ah + i4 * 4) = make_uint2(h0, h1);
    *(uint2*)(g_al + i4 * 4) = make_uint2(l0, l1);
}

// ---------------------------------------------------------------------------
// weight transpose + split: W[k][n] -> g_bh/g_bl [n][k]
// ---------------------------------------------------------------------------
__global__ __launch_bounds__(256) void transpose_split_kernel(const float* __restrict__ W)
{
    __shared__ float t[32][33];
    const int bx = blockIdx.x * 32, by = blockIdx.y * 32;
    const int tx = threadIdx.x, ty = threadIdx.y;  // 32x8
#pragma unroll
    for (int j = 0; j < 32; j += 8)
        t[ty + j][tx] = W[(size_t)(by + ty + j) * DM + bx + tx];
    __syncthreads();
#pragma unroll
    for (int j = 0; j < 32; j += 8) {
        float x = t[tx][ty + j];
        __nv_bfloat16 h = __float2bfloat16_rn(x);
        __nv_bfloat16 l = __float2bfloat16_rn(x - __bfloat162float(h));
        const size_t o = (size_t)(bx + ty + j) * DM + by + tx;
        g_bh[o] = h;
        g_bl[o] = l;
    }
}

// ---------------------------------------------------------------------------
// Projection / output GEMM, 2-stage cp.async pipelined, bf16 3-MMA split.
//   C[8192,1024] = A(g_ah/g_al) @ B^T(g_bh/g_bl) + bias
// MODE 0: write bf16-split head layout (sel 0/1/2 -> q/k/v split buffers)
// MODE 1: write fp32 plain to OutPlain
// BM=BN=128, BK=32, 256 thr, warps 2m x 4n (warp tile 64x32).
// ---------------------------------------------------------------------------
#define LDA 40
#define GT  (128 * LDA * 2)          // 10240 B per tile buffer
#define G_SMEM (8 * GT)              // 81920 B

template <int MODE>
__global__ __launch_bounds__(256) void mma_gemm(
    const float* __restrict__ bias, float* __restrict__ OutPlain, int sel)
{
    extern __shared__ char sm[];
    const uint32_t smb = smem_u32(sm);

    const int tid  = threadIdx.x;
    const int wid  = tid >> 5;
    const int lane = tid & 31;
    const int m0 = blockIdx.y * 128;
    const int n0 = blockIdx.x * 128;
    const int base_m = (wid >> 2) * 64;
    const int base_n = (wid & 3) * 32;
    const int grow = tid >> 2;
    const int gch  = (tid & 3) * 8;

    const uint32_t a_lane = (uint32_t)(((lane & 15) * LDA + (lane >> 4) * 8) * 2);
    const uint32_t b_lane = (uint32_t)(((((lane >> 4) & 1) * 8 + (lane & 7)) * LDA
                                        + ((lane >> 3) & 1) * 8) * 2);

    const uint32_t so0 = (uint32_t)(grow * (LDA * 2) + gch * 2);
    const uint32_t so1 = so0 + 64 * (LDA * 2);

    float c[4][4][4];
#pragma unroll
    for (int i = 0; i < 4; i++)
#pragma unroll
        for (int j = 0; j < 4; j++)
#pragma unroll
            for (int r = 0; r < 4; r++) c[i][j][r] = 0.f;

    auto prefetch = [&](int kt, int st) {
        const size_t a0 = (size_t)(m0 + grow) * DM + kt * 32 + gch;
        const size_t b0 = (size_t)(n0 + grow) * DM + kt * 32 + gch;
        const uint32_t aH = smb + 0 * GT * 2 + st * GT;
        const uint32_t aL = smb + 1 * GT * 2 + st * GT;
        const uint32_t bH = smb + 2 * GT * 2 + st * GT;
        const uint32_t bL = smb + 3 * GT * 2 + st * GT;
        CP16(aH + so0, g_ah + a0); CP16(aH + so1, g_ah + a0 + (size_t)64 * DM);
        CP16(aL + so0, g_al + a0); CP16(aL + so1, g_al + a0 + (size_t)64 * DM);
        CP16(bH + so0, g_bh + b0); CP16(bH + so1, g_bh + b0 + (size_t)64 * DM);
        CP16(bL + so0, g_bl + b0); CP16(bL + so1, g_bl + b0 + (size_t)64 * DM);
    };

    prefetch(0, 0);
    CP_COMMIT();

    for (int kt = 0; kt < 32; kt++) {
        const int cur = kt & 1;
        CP_WAIT0();
        __syncthreads();
        if (kt < 31) { prefetch(kt + 1, cur ^ 1); CP_COMMIT(); }

        const uint32_t aH = smb + 0 * GT * 2 + cur * GT;
        const uint32_t aL = smb + 1 * GT * 2 + cur * GT;
        const uint32_t bH = smb + 2 * GT * 2 + cur * GT;
        const uint32_t bL = smb + 3 * GT * 2 + cur * GT;

#pragma unroll
        for (int ks = 0; ks < 2; ks++) {
            uint32_t bh[8], bl[8];
#pragma unroll
            for (int ni2 = 0; ni2 < 2; ni2++) {
                const uint32_t bo = (uint32_t)((base_n + ni2 * 16) * (LDA * 2) + ks * 32) + b_lane;
                LDMX4(bh[ni2*4+0], bh[ni2*4+1], bh[ni2*4+2], bh[ni2*4+3], bH + bo);
                LDMX4(bl[ni2*4+0], bl[ni2*4+1], bl[ni2*4+2], bl[ni2*4+3], bL + bo);
            }
#pragma unroll
            for (int mi = 0; mi < 4; mi++) {
                const uint32_t ao = (uint32_t)((base_m + mi * 16) * (LDA * 2) + ks * 32) + a_lane;
                uint32_t ah[4], al[4];
                LDMX4(ah[0], ah[1], ah[2], ah[3], aH + ao);
                LDMX4(al[0], al[1], al[2], al[3], aL + ao);
#pragma unroll
                for (int ni = 0; ni < 4; ni++) {
                    const int bi = (ni >> 1) * 4 + (ni & 1) * 2;
                    MMA16816(c[mi][ni], ah, bh[bi], bh[bi + 1]);
                    MMA16816(c[mi][ni], ah, bl[bi], bl[bi + 1]);
                    MMA16816(c[mi][ni], al, bh[bi], bh[bi + 1]);
                }
            }
        }
        __syncthreads();
    }

    // epilogue
    const int lr = lane >> 2;
    const int lc = (lane & 3) * 2;
#pragma unroll
    for (int mi = 0; mi < 4; mi++) {
#pragma unroll
        for (int ni = 0; ni < 4; ni++) {
            const int gm = m0 + base_m + mi * 16 + lr;
            const int gn = n0 + base_n + ni * 8 + lc;
            float2 bv = *(const float2*)(bias + gn);
            float2 o0 = make_float2(c[mi][ni][0] + bv.x, c[mi][ni][1] + bv.y);
            float2 o1 = make_float2(c[mi][ni][2] + bv.x, c[mi][ni][3] + bv.y);
            if (MODE == 0) {
                __nv_bfloat16* Oh = (sel == 0) ? g_qsh : (sel == 1) ? g_ksh : g_vsh;
                __nv_bfloat16* Ol = (sel == 0) ? g_qsl : (sel == 1) ? g_ksl : g_vsl;
                const int h = gn >> 6, dk = gn & 63;
                uint32_t hi, lo;
                {
                    const int b = gm >> 10, s = gm & 1023;
                    const size_t idx = (((size_t)(b * NH + h)) * SEQL + s) * DK + dk;
                    split2(o0.x, o0.y, hi, lo);
                    *(uint32_t*)(Oh + idx) = hi;
                    *(uint32_t*)(Ol + idx) = lo;
                }
                {
                    const int m2 = gm + 8;
                    const int b = m2 >> 10, s = m2 & 1023;
                    const size_t idx = (((size_t)(b * NH + h)) * SEQL + s) * DK + dk;
                    split2(o1.x, o1.y, hi, lo);
                    *(uint32_t*)(Oh + idx) = hi;
                    *(uint32_t*)(Ol + idx) = lo;
                }
            } else {
                *(float2*)&OutPlain[(size_t)gm * DM + gn] = o0;
                *(float2*)&OutPlain[(size_t)(gm + 8) * DM + gn] = o1;
            }
        }
    }
}

// ---------------------------------------------------------------------------
// Scores via MMA: per z=(b,h): S[128,128 tile] = (Q @ K^T)*0.125, mask->-1e9
// K dim = 64 (single SMEM stage). 256 thr, warps 2m x 4n.
// ---------------------------------------------------------------------------
#define SLD 72
#define ST  (128 * SLD * 2)          // 18432 B
#define S_SMEM (4 * ST)              // 73728 B

__global__ __launch_bounds__(256) void scores_mma(const int* __restrict__ mask)
{
    extern __shared__ char sm[];
    const uint32_t smb = smem_u32(sm);
    const uint32_t qH = smb, qL = smb + ST, kH = smb + 2 * ST, kL = smb + 3 * ST;

    const int tid  = threadIdx.x;
    const int wid  = tid >> 5;
    const int lane = tid & 31;
    const int z = blockIdx.z;
    const int b = z >> 4;
    const int m0 = blockIdx.y * 128;
    const int n0 = blockIdx.x * 128;

    const __nv_bfloat16* Qh = g_qsh + (size_t)z * SEQL * DK;
    const __nv_bfloat16* Ql = g_qsl + (size_t)z * SEQL * DK;
    const __nv_bfloat16* Kh = g_ksh + (size_t)z * SEQL * DK;
    const __nv_bfloat16* Kl = g_ksl + (size_t)z * SEQL * DK;

    // load full 128x64 tiles
    {
        const int row = tid >> 1;
        const int cb  = (tid & 1) * 32;
#pragma unroll
        for (int i = 0; i < 4; i++) {
            const int col = cb + i * 8;
            const uint32_t so = (uint32_t)(row * (SLD * 2) + col * 2);
            const size_t qo = (size_t)(m0 + row) * DK + col;
            const size_t ko = (size_t)(n0 + row) * DK + col;
            CP16(qH + so, Qh + qo);
            CP16(qL + so, Ql + qo);
            CP16(kH + so, Kh + ko);
            CP16(kL + so, Kl + ko);
        }
    }
    CP_COMMIT();
    CP_WAIT0();
    __syncthreads();

    const int base_m = (wid >> 2) * 64;
    const int base_n = (wid & 3) * 32;
    const uint32_t a_lane = (uint32_t)(((lane & 15) * SLD + (lane >> 4) * 8) * 2);
    const uint32_t b_lane = (uint32_t)(((((lane >> 4) & 1) * 8 + (lane & 7)) * SLD
                                        + ((lane >> 3) & 1) * 8) * 2);

    float c[4][4][4];
#pragma unroll
    for (int i = 0; i < 4; i++)
#pragma unroll
        for (int j = 0; j < 4; j++)
#pragma unroll
            for (int r = 0; r < 4; r++) c[i][j][r] = 0.f;

#pragma unroll
    for (int ks = 0; ks < 4; ks++) {
        uint32_t bh[8], bl[8];
#pragma unroll
        for (int ni2 = 0; ni2 < 2; ni2++) {
            const uint32_t bo = (uint32_t)((base_n + ni2 * 16) * (SLD * 2) + ks * 32) + b_lane;
            LDMX4(bh[ni2*4+0], bh[ni2*4+1], bh[ni2*4+2], bh[ni2*4+3], kH + bo);
            LDMX4(bl[ni2*4+0], bl[ni2*4+1], bl[ni2*4+2], bl[ni2*4+3], kL + bo);
        }
#pragma unroll
        for (int mi = 0; mi < 4; mi++) {
            const uint32_t ao = (uint32_t)((base_m + mi * 16) * (SLD * 2) + ks * 32) + a_lane;
            uint32_t ah[4], al[4];
            LDMX4(ah[0], ah[1], ah[2], ah[3], qH + ao);
            LDMX4(al[0], al[1], al[2], al[3], qL + ao);
#pragma unroll
            for (int ni = 0; ni < 4; ni++) {
                const int bi = (ni >> 1) * 4 + (ni & 1) * 2;
                MMA16816(c[mi][ni], ah, bh[bi], bh[bi + 1]);
                MMA16816(c[mi][ni], ah, bl[bi], bl[bi + 1]);
                MMA16816(c[mi][ni], al, bh[bi], bh[bi + 1]);
            }
        }
    }

    // epilogue: scale + mask + store fp32
    float* __restrict__ S = g_sc + (size_t)z * SEQL * SEQL;
    const int* __restrict__ M = mask + (size_t)b * SEQL * SEQL;
    const int lr = lane >> 2;
    const int lc = (lane & 3) * 2;
#pragma unroll
    for (int mi = 0; mi < 4; mi++) {
#pragma unroll
        for (int ni = 0; ni < 4; ni++) {
            const int gm = m0 + base_m + mi * 16 + lr;
            const int gn = n0 + base_n + ni * 8 + lc;
            {
                int2 mk = *(const int2*)&M[(size_t)gm * SEQL + gn];
                float2 o;
                o.x = mk.x ? c[mi][ni][0] * 0.125f : -1e9f;
                o.y = mk.y ? c[mi][ni][1] * 0.125f : -1e9f;
                *(float2*)&S[(size_t)gm * SEQL + gn] = o;
            }
            {
                int2 mk = *(const int2*)&M[(size_t)(gm + 8) * SEQL + gn];
                float2 o;
                o.x = mk.x ? c[mi][ni][2] * 0.125f : -1e9f;
                o.y = mk.y ? c[mi][ni][3] * 0.125f : -1e9f;
                *(float2*)&S[(size_t)(gm + 8) * SEQL + gn] = o;
            }
        }
    }
}

// ---------------------------------------------------------------------------
// Softmax over last dim (1024); reads g_sc fp32, writes split bf16 g_ph/g_pl.
// ---------------------------------------------------------------------------
__global__ __launch_bounds__(256) void softmax_kernel()
{
    const size_t row = blockIdx.x;
    const float4* __restrict__ p = (const float4*)(g_sc + row * SEQL);
    const int tid = threadIdx.x;

    float4 v = p[tid];
    float mx = fmaxf(fmaxf(v.x, v.y), fmaxf(v.z, v.w));
#pragma unroll
    for (int o = 16; o; o >>= 1) mx = fmaxf(mx, __shfl_xor_sync(0xffffffffu, mx, o));

    __shared__ float smax[8];
    __shared__ float ssum[8];
    if ((tid & 31) == 0) smax[tid >> 5] = mx;
    __syncthreads();
    mx = smax[0];
#pragma unroll
    for (int w = 1; w < 8; w++) mx = fmaxf(mx, smax[w]);

    float e0 = __expf(v.x - mx), e1 = __expf(v.y - mx);
    float e2 = __expf(v.z - mx), e3 = __expf(v.w - mx);
    float s = e0 + e1 + e2 + e3;
#pragma unroll
    for (int o = 16; o; o >>= 1) s += __shfl_xor_sync(0xffffffffu, s, o);
    if ((tid & 31) == 0) ssum[tid >> 5] = s;
    __syncthreads();
    s = ssum[0];
#pragma unroll
    for (int w = 1; w < 8; w++) s += ssum[w];

    const float inv = 1.f / s;
    uint32_t h01, l01, h23, l23;
    split2(e0 * inv, e1 * inv, h01, l01);
    split2(e2 * inv, e3 * inv, h23, l23);
    *(uint2*)(g_ph + row * SEQL + tid * 4) = make_uint2(h01, h23);
    *(uint2*)(g_pl + row * SEQL + tid * 4) = make_uint2(l01, l23);
}

// ---------------------------------------------------------------------------
// Context via MMA: per z: C[1024,64] = P @ V.  P split A; V split B (ldmatrix.trans).
// BM=128, BN=64, BK=32, 2-stage cp.async. 8 warps: 4m x 2n (warp 32m x 32n).
// Epilogue writes ctx as split bf16 into g_ah/g_al plain layout for the final GEMM.
// ---------------------------------------------------------------------------
#define CAT (128 * LDA * 2)          // 10240 (P tile, LDA=40)
#define CBT (32 * SLD * 2)           // 4608  (V tile, SLD=72)
#define C_SMEM (4 * CAT + 4 * CBT)   // 59392

__global__ __launch_bounds__(256) void ctx_mma()
{
    extern __shared__ char sm[];
    const uint32_t smb = smem_u32(sm);

    const int tid  = threadIdx.x;
    const int wid  = tid >> 5;
    const int lane = tid & 31;
    const int z  = blockIdx.z;
    const int m0 = blockIdx.y * 128;

    const __nv_bfloat16* Ph = g_ph + (size_t)z * SEQL * SEQL;
    const __nv_bfloat16* Pl = g_pl + (size_t)z * SEQL * SEQL;
    const __nv_bfloat16* Vh = g_vsh + (size_t)z * SEQL * DK;
    const __nv_bfloat16* Vl = g_vsl + (size_t)z * SEQL * DK;

    const int wm = wid >> 1;             // 0..3
    const int wn = wid & 1;              // 0..1
    const int base_m = wm * 32;
    const int base_n = wn * 32;

    const uint32_t a_lane = (uint32_t)(((lane & 15) * LDA + (lane >> 4) * 8) * 2);
    const uint32_t t_lane = (uint32_t)(((lane & 15) * SLD + (lane >> 4) * 8) * 2);

    // load mappings
    const int prow = tid >> 1;                 // 0..127
    const int pcb  = (tid & 1) * 16;           // 2 chunks of 8
    const int vrow = tid >> 3;                 // 0..31
    const int vcol = (tid & 7) * 8;            // 0..56

    auto prefetch = [&](int kt, int st) {
        const uint32_t pH = smb + 0 * CAT * 2 + st * CAT;
        const uint32_t pL = smb + 1 * CAT * 2 + st * CAT;
        const uint32_t vH = smb + 4 * CAT + 0 * CBT * 2 + st * CBT;
        const uint32_t vL = smb + 4 * CAT + 1 * CBT * 2 + st * CBT;
#pragma unroll
        for (int i = 0; i < 2; i++) {
            const int col = pcb + i * 8;
            const uint32_t so = (uint32_t)(prow * (LDA * 2) + col * 2);
            const size_t go = (size_t)(m0 + prow) * SEQL + kt * 32 + col;
            CP16(pH + so, Ph + go);
            CP16(pL + so, Pl + go);
        }
        {
            const uint32_t so = (uint32_t)(vrow * (SLD * 2) + vcol * 2);
            const size_t go = (size_t)(kt * 32 + vrow) * DK + vcol;
            CP16(vH + so, Vh + go);
            CP16(vL + so, Vl + go);
        }
    };

    float c[2][4][4];
#pragma unroll
    for (int i = 0; i < 2; i++)
#pragma unroll
        for (int j = 0; j < 4; j++)
#pragma unroll
            for (int r = 0; r < 4; r++) c[i][j][r] = 0.f;

    prefetch(0, 0);
    CP_COMMIT();

    for (int kt = 0; kt < 32; kt++) {
        const int cur = kt & 1;
        CP_WAIT0();
        __syncthreads();
        if (kt < 31) { prefetch(kt + 1, cur ^ 1); CP_COMMIT(); }

        const uint32_t pH = smb + 0 * CAT * 2 + cur * CAT;
        const uint32_t pL = smb + 1 * CAT * 2 + cur * CAT;
        const uint32_t vH = smb + 4 * CAT + 0 * CBT * 2 + cur * CBT;
        const uint32_t vL = smb + 4 * CAT + 1 * CBT * 2 + cur * CBT;

#pragma unroll
        for (int ks = 0; ks < 2; ks++) {
            uint32_t bh[8], bl[8];
#pragma unroll
            for (int nh = 0; nh < 2; nh++) {
                const uint32_t bo = (uint32_t)(ks * 16 * (SLD * 2) + (base_n + nh * 16) * 2) + t_lane;
                LDMX4T(bh[nh*4+0], bh[nh*4+1], bh[nh*4+2], bh[nh*4+3], vH + bo);
                LDMX4T(bl[nh*4+0], bl[nh*4+1], bl[nh*4+2], bl[nh*4+3], vL + bo);
            }
#pragma unroll
            for (int mi = 0; mi < 2; mi++) {
                const uint32_t ao = (uint32_t)((base_m + mi * 16) * (LDA * 2) + ks * 32) + a_lane;
                uint32_t ah[4], al[4];
                LDMX4(ah[0], ah[1], ah[2], ah[3], pH + ao);
                LDMX4(al[0], al[1], al[2], al[3], pL + ao);
#pragma unroll
                for (int ni = 0; ni < 4; ni++) {
                    const int bi = (ni >> 1) * 4 + (ni & 1) * 2;
                    MMA16816(c[mi][ni], ah, bh[bi], bh[bi + 1]);
                    MMA16816(c[mi][ni], ah, bl[bi], bl[bi + 1]);
                    MMA16816(c[mi][ni], al, bh[bi], bh[bi + 1]);
                }
            }
        }
        __syncthreads();
    }

    // epilogue: write split bf16 ctx into plain [b*1024+s][h*64+dk] layout
    const int b = z >> 4, h = z & 15;
    const int lr = lane >> 2;
    const int lc = (lane & 3) * 2;
#pragma unroll
    for (int mi = 0; mi < 2; mi++) {
#pragma unroll
        for (int ni = 0; ni < 4; ni++) {
            const int s0 = m0 + base_m + mi * 16 + lr;
            const int col = h * 64 + base_n + ni * 8 + lc;
            uint32_t hi, lo;
            split2(c[mi][ni][0], c[mi][ni][1], hi, lo);
            {
                const size_t o = (size_t)(b * SEQL + s0) * DM + col;
                *(uint32_t*)(g_ah + o) = hi;
                *(uint32_t*)(g_al + o) = lo;
            }
            split2(c[mi][ni][2], c[mi][ni][3], hi, lo);
            {
                const size_t o = (size_t)(b * SEQL + s0 + 8) * DM + col;
                *(uint32_t*)(g_ah + o) = hi;
                *(uint32_t*)(g_al + o) = lo;
            }
        }
    }
}

// ===========================================================================
extern "C" void kernel_launch(void* const* d_in, const int* in_sizes, int n_in,
                              void* d_out, int out_size)
{
    const float* q    = (const float*)d_in[0];
    const float* k    = (const float*)d_in[1];
    const float* v    = (const float*)d_in[2];
    const int*   mask = (const int*)  d_in[3];
    const float* Wq   = (const float*)d_in[4];
    const float* bq   = (const float*)d_in[5];
    const float* Wk   = (const float*)d_in[6];
    const float* bk   = (const float*)d_in[7];
    const float* Wv   = (const float*)d_in[8];
    const float* bv   = (const float*)d_in[9];
    const float* Wo   = (const float*)d_in[10];
    const float* bo   = (const float*)d_in[11];
    float* out = (float*)d_out;

    cudaFuncSetAttribute(mma_gemm<0>, cudaFuncAttributeMaxDynamicSharedMemorySize, G_SMEM);
    cudaFuncSetAttribute(mma_gemm<1>, cudaFuncAttributeMaxDynamicSharedMemorySize, G_SMEM);
    cudaFuncSetAttribute(scores_mma,  cudaFuncAttributeMaxDynamicSharedMemorySize, S_SMEM);
    cudaFuncSetAttribute(ctx_mma,     cudaFuncAttributeMaxDynamicSharedMemorySize, C_SMEM);

    dim3 gb(256);
    const int nSplit = (BSZ * SEQL * DM) / 4 / 256;
    dim3 tb(32, 8);
    dim3 tg(DM / 32, DM / 32);
    dim3 gg(DM / 128, (BSZ * SEQL) / 128);

    split_input_kernel<<<nSplit, gb>>>(q);
    transpose_split_kernel<<<tg, tb>>>(Wq);
    mma_gemm<0><<<gg, gb, G_SMEM>>>(bq, nullptr, 0);

    split_input_kernel<<<nSplit, gb>>>(k);
    transpose_split_kernel<<<tg, tb>>>(Wk);
    mma_gemm<0><<<gg, gb, G_SMEM>>>(bk, nullptr, 1);

    split_input_kernel<<<nSplit, gb>>>(v);
    transpose_split_kernel<<<tg, tb>>>(Wv);
    mma_gemm<0><<<gg, gb, G_SMEM>>>(bv, nullptr, 2);

    dim3 gSc(SEQL / 128, SEQL / 128, ZTOT);
    scores_mma<<<gSc, gb, S_SMEM>>>(mask);

    softmax_kernel<<<ZTOT * SEQL, 256>>>();

    dim3 gCtx(1, SEQL / 128, ZTOT);
    ctx_mma<<<gCtx, gb, C_SMEM>>>();

    transpose_split_kernel<<<tg, tb>>>(Wo);
    mma_gemm<1><<<gg, gb, G_SMEM>>>(bo, out, 0);
}

// round 14
// speedup vs baseline: 2.6495x; 1.2483x over previous
#include <cuda_runtime.h>
#include <cuda_bf16.h>
#include <cstdint>

#define BSZ 8
#define NH 16
#define SEQL 1024
#define DM 1024
#define DK 64
#define ZTOT (BSZ*NH)

// ---------------------------------------------------------------------------
// Device scratch (static — no allocation)
// ---------------------------------------------------------------------------
static __device__ __align__(16) __nv_bfloat16 g_qsh[(size_t)ZTOT*SEQL*DK];
static __device__ __align__(16) __nv_bfloat16 g_qsl[(size_t)ZTOT*SEQL*DK];
static __device__ __align__(16) __nv_bfloat16 g_ksh[(size_t)ZTOT*SEQL*DK];
static __device__ __align__(16) __nv_bfloat16 g_ksl[(size_t)ZTOT*SEQL*DK];
static __device__ __align__(16) __nv_bfloat16 g_vsh[(size_t)ZTOT*SEQL*DK];
static __device__ __align__(16) __nv_bfloat16 g_vsl[(size_t)ZTOT*SEQL*DK];
static __device__ __align__(16) __nv_bfloat16 g_ah [(size_t)BSZ*SEQL*DM];     // A hi (inputs / ctx)
static __device__ __align__(16) __nv_bfloat16 g_al [(size_t)BSZ*SEQL*DM];     // A lo
static __device__ __align__(16) __nv_bfloat16 g_bh [(size_t)DM*DM];           // W^T hi [N][K]
static __device__ __align__(16) __nv_bfloat16 g_bl [(size_t)DM*DM];           // W^T lo

// ---------------------------------------------------------------------------
// helpers
// ---------------------------------------------------------------------------
__device__ __forceinline__ uint32_t smem_u32(const void* p) {
    uint32_t a;
    asm("{ .reg .u64 t; cvta.to.shared.u64 t, %1; cvt.u32.u64 %0, t; }" : "=r"(a) : "l"(p));
    return a;
}

#define LDMX4(r0, r1, r2, r3, addr) \
    asm volatile("ldmatrix.sync.aligned.m8n8.x4.shared.b16 {%0,%1,%2,%3}, [%4];" \
        : "=r"(r0), "=r"(r1), "=r"(r2), "=r"(r3) : "r"(addr))

#define LDMX4T(r0, r1, r2, r3, addr) \
    asm volatile("ldmatrix.sync.aligned.m8n8.x4.trans.shared.b16 {%0,%1,%2,%3}, [%4];" \
        : "=r"(r0), "=r"(r1), "=r"(r2), "=r"(r3) : "r"(addr))

#define MMA16816(c, a, b0, b1) \
    asm volatile("mma.sync.aligned.m16n8k16.row.col.f32.bf16.bf16.f32 " \
        "{%0,%1,%2,%3}, {%4,%5,%6,%7}, {%8,%9}, {%0,%1,%2,%3};" \
        : "+f"((c)[0]), "+f"((c)[1]), "+f"((c)[2]), "+f"((c)[3]) \
        : "r"((a)[0]), "r"((a)[1]), "r"((a)[2]), "r"((a)[3]), "r"(b0), "r"(b1))

#define CP16(saddr, gptr) \
    asm volatile("cp.async.cg.shared.global [%0], [%1], 16;" :: "r"((uint32_t)(saddr)), "l"(gptr))
#define CP_COMMIT() asm volatile("cp.async.commit_group;" ::: "memory")
#define CP_WAIT0()  asm volatile("cp.async.wait_group 0;" ::: "memory")
#define CP_WAIT1()  asm volatile("cp.async.wait_group 1;" ::: "memory")

__device__ __forceinline__ void split2(float x, float y, uint32_t& hi, uint32_t& lo) {
    __nv_bfloat16 hx = __float2bfloat16_rn(x);
    __nv_bfloat16 hy = __float2bfloat16_rn(y);
    __nv_bfloat162 hp(hx, hy);
    __nv_bfloat162 lp = __floats2bfloat162_rn(x - __bfloat162float(hx),
                                              y - __bfloat162float(hy));
    hi = *(uint32_t*)&hp;
    lo = *(uint32_t*)&lp;
}

// ---------------------------------------------------------------------------
// input split: fp32 [n] -> g_ah/g_al bf16
// ---------------------------------------------------------------------------
__global__ __launch_bounds__(256) void split_input_kernel(const float* __restrict__ src)
{
    const size_t i4 = (size_t)blockIdx.x * 256 + threadIdx.x;
    float4 x = *(const float4*)(src + i4 * 4);
    uint32_t h0, l0, h1, l1;
    split2(x.x, x.y, h0, l0);
    split2(x.z, x.w, h1, l1);
    *(uint2*)(g_ah + i4 * 4) = make_uint2(h0, h1);
    *(uint2*)(g_al + i4 * 4) = make_uint2(l0, l1);
}

// ---------------------------------------------------------------------------
// weight transpose + split: W[k][n] -> g_bh/g_bl [n][k]
// ---------------------------------------------------------------------------
__global__ __launch_bounds__(256) void transpose_split_kernel(const float* __restrict__ W)
{
    __shared__ float t[32][33];
    const int bx = blockIdx.x * 32, by = blockIdx.y * 32;
    const int tx = threadIdx.x, ty = threadIdx.y;  // 32x8
#pragma unroll
    for (int j = 0; j < 32; j += 8)
        t[ty + j][tx] = W[(size_t)(by + ty + j) * DM + bx + tx];
    __syncthreads();
#pragma unroll
    for (int j = 0; j < 32; j += 8) {
        float x = t[tx][ty + j];
        __nv_bfloat16 h = __float2bfloat16_rn(x);
        __nv_bfloat16 l = __float2bfloat16_rn(x - __bfloat162float(h));
        const size_t o = (size_t)(bx + ty + j) * DM + by + tx;
        g_bh[o] = h;
        g_bl[o] = l;
    }
}

// ---------------------------------------------------------------------------
// Projection / output GEMM, 2-stage cp.async pipelined, bf16 3-MMA split.
// MODE 0: write bf16-split head layout (sel 0/1/2 -> q/k/v split buffers)
// MODE 1: write fp32 plain to OutPlain
// BM=BN=128, BK=32, 256 thr, warps 2m x 4n (warp tile 64x32).
// ---------------------------------------------------------------------------
#define LDA 40
#define GT  (128 * LDA * 2)
#define G_SMEM (8 * GT)

template <int MODE>
__global__ __launch_bounds__(256) void mma_gemm(
    const float* __restrict__ bias, float* __restrict__ OutPlain, int sel)
{
    extern __shared__ char sm[];
    const uint32_t smb = smem_u32(sm);

    const int tid  = threadIdx.x;
    const int wid  = tid >> 5;
    const int lane = tid & 31;
    const int m0 = blockIdx.y * 128;
    const int n0 = blockIdx.x * 128;
    const int base_m = (wid >> 2) * 64;
    const int base_n = (wid & 3) * 32;
    const int grow = tid >> 2;
    const int gch  = (tid & 3) * 8;

    const uint32_t a_lane = (uint32_t)(((lane & 15) * LDA + (lane >> 4) * 8) * 2);
    const uint32_t b_lane = (uint32_t)(((((lane >> 4) & 1) * 8 + (lane & 7)) * LDA
                                        + ((lane >> 3) & 1) * 8) * 2);

    const uint32_t so0 = (uint32_t)(grow * (LDA * 2) + gch * 2);
    const uint32_t so1 = so0 + 64 * (LDA * 2);

    float c[4][4][4];
#pragma unroll
    for (int i = 0; i < 4; i++)
#pragma unroll
        for (int j = 0; j < 4; j++)
#pragma unroll
            for (int r = 0; r < 4; r++) c[i][j][r] = 0.f;

    auto prefetch = [&](int kt, int st) {
        const size_t a0 = (size_t)(m0 + grow) * DM + kt * 32 + gch;
        const size_t b0 = (size_t)(n0 + grow) * DM + kt * 32 + gch;
        const uint32_t aH = smb + 0 * GT * 2 + st * GT;
        const uint32_t aL = smb + 1 * GT * 2 + st * GT;
        const uint32_t bH = smb + 2 * GT * 2 + st * GT;
        const uint32_t bL = smb + 3 * GT * 2 + st * GT;
        CP16(aH + so0, g_ah + a0); CP16(aH + so1, g_ah + a0 + (size_t)64 * DM);
        CP16(aL + so0, g_al + a0); CP16(aL + so1, g_al + a0 + (size_t)64 * DM);
        CP16(bH + so0, g_bh + b0); CP16(bH + so1, g_bh + b0 + (size_t)64 * DM);
        CP16(bL + so0, g_bl + b0); CP16(bL + so1, g_bl + b0 + (size_t)64 * DM);
    };

    prefetch(0, 0);
    CP_COMMIT();

    for (int kt = 0; kt < 32; kt++) {
        const int cur = kt & 1;
        CP_WAIT0();
        __syncthreads();
        if (kt < 31) { prefetch(kt + 1, cur ^ 1); CP_COMMIT(); }

        const uint32_t aH = smb + 0 * GT * 2 + cur * GT;
        const uint32_t aL = smb + 1 * GT * 2 + cur * GT;
        const uint32_t bH = smb + 2 * GT * 2 + cur * GT;
        const uint32_t bL = smb + 3 * GT * 2 + cur * GT;

#pragma unroll
        for (int ks = 0; ks < 2; ks++) {
            uint32_t bh[8], bl[8];
#pragma unroll
            for (int ni2 = 0; ni2 < 2; ni2++) {
                const uint32_t bo = (uint32_t)((base_n + ni2 * 16) * (LDA * 2) + ks * 32) + b_lane;
                LDMX4(bh[ni2*4+0], bh[ni2*4+1], bh[ni2*4+2], bh[ni2*4+3], bH + bo);
                LDMX4(bl[ni2*4+0], bl[ni2*4+1], bl[ni2*4+2], bl[ni2*4+3], bL + bo);
            }
#pragma unroll
            for (int mi = 0; mi < 4; mi++) {
                const uint32_t ao = (uint32_t)((base_m + mi * 16) * (LDA * 2) + ks * 32) + a_lane;
                uint32_t ah[4], al[4];
                LDMX4(ah[0], ah[1], ah[2], ah[3], aH + ao);
                LDMX4(al[0], al[1], al[2], al[3], aL + ao);
#pragma unroll
                for (int ni = 0; ni < 4; ni++) {
                    const int bi = (ni >> 1) * 4 + (ni & 1) * 2;
                    MMA16816(c[mi][ni], ah, bh[bi], bh[bi + 1]);
                    MMA16816(c[mi][ni], ah, bl[bi], bl[bi + 1]);
                    MMA16816(c[mi][ni], al, bh[bi], bh[bi + 1]);
                }
            }
        }
        __syncthreads();
    }

    const int lr = lane >> 2;
    const int lc = (lane & 3) * 2;
#pragma unroll
    for (int mi = 0; mi < 4; mi++) {
#pragma unroll
        for (int ni = 0; ni < 4; ni++) {
            const int gm = m0 + base_m + mi * 16 + lr;
            const int gn = n0 + base_n + ni * 8 + lc;
            float2 bv = *(const float2*)(bias + gn);
            float2 o0 = make_float2(c[mi][ni][0] + bv.x, c[mi][ni][1] + bv.y);
            float2 o1 = make_float2(c[mi][ni][2] + bv.x, c[mi][ni][3] + bv.y);
            if (MODE == 0) {
                __nv_bfloat16* Oh = (sel == 0) ? g_qsh : (sel == 1) ? g_ksh : g_vsh;
                __nv_bfloat16* Ol = (sel == 0) ? g_qsl : (sel == 1) ? g_ksl : g_vsl;
                const int h = gn >> 6, dk = gn & 63;
                uint32_t hi, lo;
                {
                    const int b = gm >> 10, s = gm & 1023;
                    const size_t idx = (((size_t)(b * NH + h)) * SEQL + s) * DK + dk;
                    split2(o0.x, o0.y, hi, lo);
                    *(uint32_t*)(Oh + idx) = hi;
                    *(uint32_t*)(Ol + idx) = lo;
                }
                {
                    const int m2 = gm + 8;
                    const int b = m2 >> 10, s = m2 & 1023;
                    const size_t idx = (((size_t)(b * NH + h)) * SEQL + s) * DK + dk;
                    split2(o1.x, o1.y, hi, lo);
                    *(uint32_t*)(Oh + idx) = hi;
                    *(uint32_t*)(Ol + idx) = lo;
                }
            } else {
                *(float2*)&OutPlain[(size_t)gm * DM + gn] = o0;
                *(float2*)&OutPlain[(size_t)(gm + 8) * DM + gn] = o1;
            }
        }
    }
}

// ---------------------------------------------------------------------------
// Flash attention: fused scores + softmax + P@V. One block = (z, 128 Q rows).
// 8 warps, each owns 16 Q rows x full K. S and P live in registers only.
// K/V tiles (128x64 bf16 hi/lo) double-buffered via cp.async.
// Epilogue writes ctx split bf16 into g_ah/g_al plain layout.
// ---------------------------------------------------------------------------
#define FLD 72
#define FTB (128 * FLD * 2)          // 18432 B per tile
#define F_QH 0
#define F_QL FTB
#define F_KH (2 * FTB)
#define F_KL (4 * FTB)
#define F_VH (6 * FTB)
#define F_VL (8 * FTB)
#define F_SMEM (10 * FTB)            // 184320 B

__global__ __launch_bounds__(256) void flash_mma(const int* __restrict__ mask)
{
    extern __shared__ char sm[];
    const uint32_t smb = smem_u32(sm);

    const int tid  = threadIdx.x;
    const int wid  = tid >> 5;
    const int lane = tid & 31;
    const int m0 = blockIdx.x * 128;
    const int z  = blockIdx.y;
    const int b  = z >> 4, h = z & 15;

    const __nv_bfloat16* Qh = g_qsh + (size_t)z * SEQL * DK;
    const __nv_bfloat16* Ql = g_qsl + (size_t)z * SEQL * DK;
    const __nv_bfloat16* Kh = g_ksh + (size_t)z * SEQL * DK;
    const __nv_bfloat16* Kl = g_ksl + (size_t)z * SEQL * DK;
    const __nv_bfloat16* Vh = g_vsh + (size_t)z * SEQL * DK;
    const __nv_bfloat16* Vl = g_vsl + (size_t)z * SEQL * DK;
    const int* __restrict__ M = mask + (size_t)b * SEQL * SEQL;

    const int trow = tid >> 1;
    const int tcb  = (tid & 1) * 32;

    const uint32_t a_lane = (uint32_t)(((lane & 15) * FLD + (lane >> 4) * 8) * 2);
    const uint32_t b_lane = (uint32_t)(((((lane >> 4) & 1) * 8 + (lane & 7)) * FLD
                                        + ((lane >> 3) & 1) * 8) * 2);
    const uint32_t t_lane = (uint32_t)(((lane & 15) * FLD + (lane >> 4) * 8) * 2);

    auto prefetchKV = [&](int kt, int st) {
        const uint32_t kH = smb + F_KH + st * FTB;
        const uint32_t kL = smb + F_KL + st * FTB;
        const uint32_t vH = smb + F_VH + st * FTB;
        const uint32_t vL = smb + F_VL + st * FTB;
#pragma unroll
        for (int i = 0; i < 4; i++) {
            const int col = tcb + i * 8;
            const uint32_t so = (uint32_t)(trow * (FLD * 2) + col * 2);
            const size_t go = (size_t)(kt * 128 + trow) * DK + col;
            CP16(kH + so, Kh + go);
            CP16(kL + so, Kl + go);
            CP16(vH + so, Vh + go);
            CP16(vL + so, Vl + go);
        }
    };

    {
#pragma unroll
        for (int i = 0; i < 4; i++) {
            const int col = tcb + i * 8;
            const uint32_t so = (uint32_t)(trow * (FLD * 2) + col * 2);
            const size_t go = (size_t)(m0 + trow) * DK + col;
            CP16(smb + F_QH + so, Qh + go);
            CP16(smb + F_QL + so, Ql + go);
        }
    }
    CP_COMMIT();
    prefetchKV(0, 0);
    CP_COMMIT();

    CP_WAIT1();          // Q ready
    __syncthreads();

    uint32_t qfh[4][4], qfl[4][4];
#pragma unroll
    for (int ks = 0; ks < 4; ks++) {
        const uint32_t ao = (uint32_t)(wid * 16 * (FLD * 2) + ks * 32) + a_lane;
        LDMX4(qfh[ks][0], qfh[ks][1], qfh[ks][2], qfh[ks][3], smb + F_QH + ao);
        LDMX4(qfl[ks][0], qfl[ks][1], qfl[ks][2], qfl[ks][3], smb + F_QL + ao);
    }

    const int gr = lane >> 2;
    const int lc = (lane & 3) * 2;
    const int r0 = m0 + wid * 16 + gr;
    const int r1 = r0 + 8;

    float m0s = -1e30f, m1s = -1e30f;
    float l0 = 0.f, l1 = 0.f;
    float co[8][4];
#pragma unroll
    for (int j = 0; j < 8; j++)
#pragma unroll
        for (int r = 0; r < 4; r++) co[j][r] = 0.f;

    for (int kt = 0; kt < 8; kt++) {
        const int cur = kt & 1;
        CP_WAIT0();
        __syncthreads();
        if (kt < 7) { prefetchKV(kt + 1, cur ^ 1); CP_COMMIT(); }

        const uint32_t kH = smb + F_KH + cur * FTB;
        const uint32_t kL = smb + F_KL + cur * FTB;
        const uint32_t vH = smb + F_VH + cur * FTB;
        const uint32_t vL = smb + F_VL + cur * FTB;

        // ---- S = Q @ K^T (3-MMA split), warp computes 16 x 128 ----
        float cs[16][4];
#pragma unroll
        for (int j = 0; j < 16; j++)
#pragma unroll
            for (int r = 0; r < 4; r++) cs[j][r] = 0.f;

#pragma unroll
        for (int ks = 0; ks < 4; ks++) {
#pragma unroll
            for (int ni2 = 0; ni2 < 8; ni2++) {
                const uint32_t bo = (uint32_t)(ni2 * 16 * (FLD * 2) + ks * 32) + b_lane;
                uint32_t bh0, bh1, bh2, bh3, bl0, bl1, bl2, bl3;
                LDMX4(bh0, bh1, bh2, bh3, kH + bo);
                LDMX4(bl0, bl1, bl2, bl3, kL + bo);
                const int j0 = 2 * ni2;
                MMA16816(cs[j0], qfh[ks], bh0, bh1);
                MMA16816(cs[j0], qfh[ks], bl0, bl1);
                MMA16816(cs[j0], qfl[ks], bh0, bh1);
                MMA16816(cs[j0 + 1], qfh[ks], bh2, bh3);
                MMA16816(cs[j0 + 1], qfh[ks], bl2, bl3);
                MMA16816(cs[j0 + 1], qfl[ks], bh2, bh3);
            }
        }

        // ---- scale + mask ----
        const int n0 = kt * 128;
#pragma unroll
        for (int j = 0; j < 16; j++) {
            const int col = n0 + 8 * j + lc;
            int2 mk0 = *(const int2*)&M[(size_t)r0 * SEQL + col];
            int2 mk1 = *(const int2*)&M[(size_t)r1 * SEQL + col];
            cs[j][0] = mk0.x ? cs[j][0] * 0.125f : -1e9f;
            cs[j][1] = mk0.y ? cs[j][1] * 0.125f : -1e9f;
            cs[j][2] = mk1.x ? cs[j][2] * 0.125f : -1e9f;
            cs[j][3] = mk1.y ? cs[j][3] * 0.125f : -1e9f;
        }

        // ---- online softmax ----
        float mx0 = -1e30f, mx1 = -1e30f;
#pragma unroll
        for (int j = 0; j < 16; j++) {
            mx0 = fmaxf(mx0, fmaxf(cs[j][0], cs[j][1]));
            mx1 = fmaxf(mx1, fmaxf(cs[j][2], cs[j][3]));
        }
        mx0 = fmaxf(mx0, __shfl_xor_sync(0xffffffffu, mx0, 1));
        mx0 = fmaxf(mx0, __shfl_xor_sync(0xffffffffu, mx0, 2));
        mx1 = fmaxf(mx1, __shfl_xor_sync(0xffffffffu, mx1, 1));
        mx1 = fmaxf(mx1, __shfl_xor_sync(0xffffffffu, mx1, 2));

        const float mn0 = fmaxf(m0s, mx0);
        const float mn1 = fmaxf(m1s, mx1);
        const float a0 = __expf(m0s - mn0);
        const float a1 = __expf(m1s - mn1);
        m0s = mn0; m1s = mn1;

        float s0 = 0.f, s1 = 0.f;
#pragma unroll
        for (int j = 0; j < 16; j++) {
            float e0 = __expf(cs[j][0] - mn0);
            float e1 = __expf(cs[j][1] - mn0);
            float e2 = __expf(cs[j][2] - mn1);
            float e3 = __expf(cs[j][3] - mn1);
            cs[j][0] = e0; cs[j][1] = e1; cs[j][2] = e2; cs[j][3] = e3;
            s0 += e0 + e1; s1 += e2 + e3;
        }
        s0 += __shfl_xor_sync(0xffffffffu, s0, 1);
        s0 += __shfl_xor_sync(0xffffffffu, s0, 2);
        s1 += __shfl_xor_sync(0xffffffffu, s1, 1);
        s1 += __shfl_xor_sync(0xffffffffu, s1, 2);
        l0 = l0 * a0 + s0;
        l1 = l1 * a1 + s1;

#pragma unroll
        for (int j = 0; j < 8; j++) {
            co[j][0] *= a0; co[j][1] *= a0;
            co[j][2] *= a1; co[j][3] *= a1;
        }

        // ---- pack P: C-frag pairs -> A-frags (hi/lo) ----
        uint32_t ph[8][4], pl[8][4];
#pragma unroll
        for (int ks = 0; ks < 8; ks++) {
            const int j = 2 * ks;
            split2(cs[j][0], cs[j][1], ph[ks][0], pl[ks][0]);
            split2(cs[j][2], cs[j][3], ph[ks][1], pl[ks][1]);
            split2(cs[j + 1][0], cs[j + 1][1], ph[ks][2], pl[ks][2]);
            split2(cs[j + 1][2], cs[j + 1][3], ph[ks][3], pl[ks][3]);
        }

        // ---- O += P @ V (3-MMA split), V via ldmatrix.trans ----
#pragma unroll
        for (int ks = 0; ks < 8; ks++) {
#pragma unroll
            for (int nt = 0; nt < 4; nt++) {
                const uint32_t bo = (uint32_t)(ks * 16 * (FLD * 2) + nt * 16 * 2) + t_lane;
                uint32_t vh0, vh1, vh2, vh3, vl0, vl1, vl2, vl3;
                LDMX4T(vh0, vh1, vh2, vh3, vH + bo);
                LDMX4T(vl0, vl1, vl2, vl3, vL + bo);
                const int j0 = 2 * nt;
                MMA16816(co[j0], ph[ks], vh0, vh1);
                MMA16816(co[j0], ph[ks], vl0, vl1);
                MMA16816(co[j0], pl[ks], vh0, vh1);
                MMA16816(co[j0 + 1], ph[ks], vh2, vh3);
                MMA16816(co[j0 + 1], ph[ks], vl2, vl3);
                MMA16816(co[j0 + 1], pl[ks], vh2, vh3);
            }
        }
        __syncthreads();
    }

    // ---- epilogue: O /= l, split bf16, write plain [b*1024+s][h*64+col] ----
    const float inv0 = 1.f / l0;
    const float inv1 = 1.f / l1;
#pragma unroll
    for (int j = 0; j < 8; j++) {
        const int col = h * 64 + 8 * j + lc;
        uint32_t hi, lo;
        split2(co[j][0] * inv0, co[j][1] * inv0, hi, lo);
        {
            const size_t o = (size_t)(b * SEQL + r0) * DM + col;
            *(uint32_t*)(g_ah + o) = hi;
            *(uint32_t*)(g_al + o) = lo;
        }
        split2(co[j][2] * inv1, co[j][3] * inv1, hi, lo);
        {
            const size_t o = (size_t)(b * SEQL + r1) * DM + col;
            *(uint32_t*)(g_ah + o) = hi;
            *(uint32_t*)(g_al + o) = lo;
        }
    }
}

// ===========================================================================
extern "C" void kernel_launch(void* const* d_in, const int* in_sizes, int n_in,
                              void* d_out, int out_size)
{
    const float* q    = (const float*)d_in[0];
    const float* k    = (const float*)d_in[1];
    const float* v    = (const float*)d_in[2];
    const int*   mask = (const int*)  d_in[3];
    const float* Wq   = (const float*)d_in[4];
    const float* bq   = (const float*)d_in[5];
    const float* Wk   = (const float*)d_in[6];
    const float* bk   = (const float*)d_in[7];
    const float* Wv   = (const float*)d_in[8];
    const float* bv   = (const float*)d_in[9];
    const float* Wo   = (const float*)d_in[10];
    const float* bo   = (const float*)d_in[11];
    float* out = (float*)d_out;

    cudaFuncSetAttribute(mma_gemm<0>, cudaFuncAttributeMaxDynamicSharedMemorySize, G_SMEM);
    cudaFuncSetAttribute(mma_gemm<1>, cudaFuncAttributeMaxDynamicSharedMemorySize, G_SMEM);
    cudaFuncSetAttribute(flash_mma,   cudaFuncAttributeMaxDynamicSharedMemorySize, F_SMEM);

    dim3 gb(256);
    const int nSplit = (BSZ * SEQL * DM) / 4 / 256;
    dim3 tb(32, 8);
    dim3 tg(DM / 32, DM / 32);
    dim3 gg(DM / 128, (BSZ * SEQL) / 128);

    split_input_kernel<<<nSplit, gb>>>(q);
    transpose_split_kernel<<<tg, tb>>>(Wq);
    mma_gemm<0><<<gg, gb, G_SMEM>>>(bq, nullptr, 0);

    split_input_kernel<<<nSplit, gb>>>(k);
    transpose_split_kernel<<<tg, tb>>>(Wk);
    mma_gemm<0><<<gg, gb, G_SMEM>>>(bk, nullptr, 1);

    split_input_kernel<<<nSplit, gb>>>(v);
    transpose_split_kernel<<<tg, tb>>>(Wv);
    mma_gemm<0><<<gg, gb, G_SMEM>>>(bv, nullptr, 2);

    dim3 gF(SEQL / 128, ZTOT);                 // (8, 128)
    flash_mma<<<gF, gb, F_SMEM>>>(mask);

    transpose_split_kernel<<<tg, tb>>>(Wo);
    mma_gemm<1><<<gg, gb, G_SMEM>>>(bo, out, 0);
}

// round 16
// speedup vs baseline: 2.7740x; 1.0470x over previous
#include <cuda_runtime.h>
#include <cuda_bf16.h>
#include <cstdint>

#define BSZ 8
#define NH 16
#define SEQL 1024
#define DM 1024
#define DK 64
#define ZTOT (BSZ*NH)

#define ASZ ((size_t)BSZ*SEQL*DM)     // 8M elems per A slot
#define WSZ ((size_t)DM*DM)           // 1M elems per W slot

// ---------------------------------------------------------------------------
// Device scratch (static — no allocation)
// ---------------------------------------------------------------------------
static __device__ __align__(16) __nv_bfloat16 g_qsh[(size_t)ZTOT*SEQL*DK];
static __device__ __align__(16) __nv_bfloat16 g_qsl[(size_t)ZTOT*SEQL*DK];
static __device__ __align__(16) __nv_bfloat16 g_ksh[(size_t)ZTOT*SEQL*DK];
static __device__ __align__(16) __nv_bfloat16 g_ksl[(size_t)ZTOT*SEQL*DK];
static __device__ __align__(16) __nv_bfloat16 g_vsh[(size_t)ZTOT*SEQL*DK];
static __device__ __align__(16) __nv_bfloat16 g_vsl[(size_t)ZTOT*SEQL*DK];
static __device__ __align__(16) __nv_bfloat16 g_ah [3*ASZ];   // A hi: slots q,k,v (slot 0 reused for ctx)
static __device__ __align__(16) __nv_bfloat16 g_al [3*ASZ];   // A lo
static __device__ __align__(16) __nv_bfloat16 g_bh [4*WSZ];   // W^T hi: slots Wq,Wk,Wv,Wo
static __device__ __align__(16) __nv_bfloat16 g_bl [4*WSZ];   // W^T lo

// ---------------------------------------------------------------------------
// helpers
// ---------------------------------------------------------------------------
__device__ __forceinline__ uint32_t smem_u32(const void* p) {
    uint32_t a;
    asm("{ .reg .u64 t; cvta.to.shared.u64 t, %1; cvt.u32.u64 %0, t; }" : "=r"(a) : "l"(p));
    return a;
}

#define LDMX4(r0, r1, r2, r3, addr) \
    asm volatile("ldmatrix.sync.aligned.m8n8.x4.shared.b16 {%0,%1,%2,%3}, [%4];" \
        : "=r"(r0), "=r"(r1), "=r"(r2), "=r"(r3) : "r"(addr))

#define LDMX4T(r0, r1, r2, r3, addr) \
    asm volatile("ldmatrix.sync.aligned.m8n8.x4.trans.shared.b16 {%0,%1,%2,%3}, [%4];" \
        : "=r"(r0), "=r"(r1), "=r"(r2), "=r"(r3) : "r"(addr))

#define MMA16816(c, a, b0, b1) \
    asm volatile("mma.sync.aligned.m16n8k16.row.col.f32.bf16.bf16.f32 " \
        "{%0,%1,%2,%3}, {%4,%5,%6,%7}, {%8,%9}, {%0,%1,%2,%3};" \
        : "+f"((c)[0]), "+f"((c)[1]), "+f"((c)[2]), "+f"((c)[3]) \
        : "r"((a)[0]), "r"((a)[1]), "r"((a)[2]), "r"((a)[3]), "r"(b0), "r"(b1))

#define CP16(saddr, gptr) \
    asm volatile("cp.async.cg.shared.global [%0], [%1], 16;" :: "r"((uint32_t)(saddr)), "l"(gptr))
#define CP_COMMIT() asm volatile("cp.async.commit_group;" ::: "memory")
#define CP_WAIT0()  asm volatile("cp.async.wait_group 0;" ::: "memory")
#define CP_WAIT1()  asm volatile("cp.async.wait_group 1;" ::: "memory")

__device__ __forceinline__ void split2(float x, float y, uint32_t& hi, uint32_t& lo) {
    __nv_bfloat16 hx = __float2bfloat16_rn(x);
    __nv_bfloat16 hy = __float2bfloat16_rn(y);
    __nv_bfloat162 hp(hx, hy);
    __nv_bfloat162 lp = __floats2bfloat162_rn(x - __bfloat162float(hx),
                                              y - __bfloat162float(hy));
    hi = *(uint32_t*)&hp;
    lo = *(uint32_t*)&lp;
}

// ---------------------------------------------------------------------------
// merged input split: q,k,v fp32 -> g_ah/g_al slots 0,1,2 (grid.y selects)
// ---------------------------------------------------------------------------
__global__ __launch_bounds__(256) void split_qkv_kernel(
    const float* __restrict__ q, const float* __restrict__ k, const float* __restrict__ v)
{
    const int z = blockIdx.y;
    const float* src = (z == 0) ? q : (z == 1) ? k : v;
    const size_t i4 = (size_t)blockIdx.x * 256 + threadIdx.x;
    float4 x = *(const float4*)(src + i4 * 4);
    uint32_t h0, l0, h1, l1;
    split2(x.x, x.y, h0, l0);
    split2(x.z, x.w, h1, l1);
    *(uint2*)(g_ah + z * ASZ + i4 * 4) = make_uint2(h0, h1);
    *(uint2*)(g_al + z * ASZ + i4 * 4) = make_uint2(l0, l1);
}

// ---------------------------------------------------------------------------
// merged weight transpose + split: 4 weights -> g_bh/g_bl slots 0..3
// ---------------------------------------------------------------------------
__global__ __launch_bounds__(256) void transpose4_kernel(
    const float* __restrict__ Wq, const float* __restrict__ Wk,
    const float* __restrict__ Wv, const float* __restrict__ Wo)
{
    __shared__ float t[32][33];
    const int z = blockIdx.z;
    const float* W = (z == 0) ? Wq : (z == 1) ? Wk : (z == 2) ? Wv : Wo;
    const int bx = blockIdx.x * 32, by = blockIdx.y * 32;
    const int tx = threadIdx.x, ty = threadIdx.y;  // 32x8
#pragma unroll
    for (int j = 0; j < 32; j += 8)
        t[ty + j][tx] = W[(size_t)(by + ty + j) * DM + bx + tx];
    __syncthreads();
#pragma unroll
    for (int j = 0; j < 32; j += 8) {
        float x = t[tx][ty + j];
        __nv_bfloat16 h = __float2bfloat16_rn(x);
        __nv_bfloat16 l = __float2bfloat16_rn(x - __bfloat162float(h));
        const size_t o = z * WSZ + (size_t)(bx + ty + j) * DM + by + tx;
        g_bh[o] = h;
        g_bl[o] = l;
    }
}

// ---------------------------------------------------------------------------
// GEMM, 2-stage cp.async pipelined, bf16 3-MMA split, ONE sync per k-iter.
// MODE 0: grid.z = 3 (q/k/v); A slot z, B slot z; write split head layout.
// MODE 1: A slot 0 (ctx), B slot 3 (Wo); write fp32 plain to OutPlain.
// BM=BN=128, BK=32, 256 thr, warps 2m x 4n.
// ---------------------------------------------------------------------------
#define LDA 40
#define GT  (128 * LDA * 2)
#define G_SMEM (8 * GT)

template <int MODE>
__global__ __launch_bounds__(256) void mma_gemm(
    const float* __restrict__ bias0, const float* __restrict__ bias1,
    const float* __restrict__ bias2, float* __restrict__ OutPlain)
{
    extern __shared__ char sm[];
    const uint32_t smb = smem_u32(sm);

    const int tid  = threadIdx.x;
    const int wid  = tid >> 5;
    const int lane = tid & 31;
    const int m0 = blockIdx.y * 128;
    const int n0 = blockIdx.x * 128;
    const int sel = (MODE == 0) ? blockIdx.z : 0;
    const int bslot = (MODE == 0) ? sel : 3;
    const __nv_bfloat16* __restrict__ Ah = g_ah + (size_t)sel * ASZ;
    const __nv_bfloat16* __restrict__ Al = g_al + (size_t)sel * ASZ;
    const __nv_bfloat16* __restrict__ Bh = g_bh + (size_t)bslot * WSZ;
    const __nv_bfloat16* __restrict__ Bl = g_bl + (size_t)bslot * WSZ;
    const float* __restrict__ bias =
        (MODE == 1) ? bias0 : (sel == 0) ? bias0 : (sel == 1) ? bias1 : bias2;

    const int base_m = (wid >> 2) * 64;
    const int base_n = (wid & 3) * 32;
    const int grow = tid >> 2;
    const int gch  = (tid & 3) * 8;

    const uint32_t a_lane = (uint32_t)(((lane & 15) * LDA + (lane >> 4) * 8) * 2);
    const uint32_t b_lane = (uint32_t)(((((lane >> 4) & 1) * 8 + (lane & 7)) * LDA
                                        + ((lane >> 3) & 1) * 8) * 2);

    const uint32_t so0 = (uint32_t)(grow * (LDA * 2) + gch * 2);
    const uint32_t so1 = so0 + 64 * (LDA * 2);

    float c[4][4][4];
#pragma unroll
    for (int i = 0; i < 4; i++)
#pragma unroll
        for (int j = 0; j < 4; j++)
#pragma unroll
            for (int r = 0; r < 4; r++) c[i][j][r] = 0.f;

    auto prefetch = [&](int kt, int st) {
        const size_t a0 = (size_t)(m0 + grow) * DM + kt * 32 + gch;
        const size_t b0 = (size_t)(n0 + grow) * DM + kt * 32 + gch;
        const uint32_t aH = smb + 0 * GT * 2 + st * GT;
        const uint32_t aL = smb + 1 * GT * 2 + st * GT;
        const uint32_t bH = smb + 2 * GT * 2 + st * GT;
        const uint32_t bL = smb + 3 * GT * 2 + st * GT;
        CP16(aH + so0, Ah + a0); CP16(aH + so1, Ah + a0 + (size_t)64 * DM);
        CP16(aL + so0, Al + a0); CP16(aL + so1, Al + a0 + (size_t)64 * DM);
        CP16(bH + so0, Bh + b0); CP16(bH + so1, Bh + b0 + (size_t)64 * DM);
        CP16(bL + so0, Bl + b0); CP16(bL + so1, Bl + b0 + (size_t)64 * DM);
    };

    prefetch(0, 0);
    CP_COMMIT();

    for (int kt = 0; kt < 32; kt++) {
        const int cur = kt & 1;
        CP_WAIT0();
        __syncthreads();
        if (kt < 31) { prefetch(kt + 1, cur ^ 1); CP_COMMIT(); }

        const uint32_t aH = smb + 0 * GT * 2 + cur * GT;
        const uint32_t aL = smb + 1 * GT * 2 + cur * GT;
        const uint32_t bH = smb + 2 * GT * 2 + cur * GT;
        const uint32_t bL = smb + 3 * GT * 2 + cur * GT;

#pragma unroll
        for (int ks = 0; ks < 2; ks++) {
            uint32_t bh[8], bl[8];
#pragma unroll
            for (int ni2 = 0; ni2 < 2; ni2++) {
                const uint32_t bo = (uint32_t)((base_n + ni2 * 16) * (LDA * 2) + ks * 32) + b_lane;
                LDMX4(bh[ni2*4+0], bh[ni2*4+1], bh[ni2*4+2], bh[ni2*4+3], bH + bo);
                LDMX4(bl[ni2*4+0], bl[ni2*4+1], bl[ni2*4+2], bl[ni2*4+3], bL + bo);
            }
#pragma unroll
            for (int mi = 0; mi < 4; mi++) {
                const uint32_t ao = (uint32_t)((base_m + mi * 16) * (LDA * 2) + ks * 32) + a_lane;
                uint32_t ah[4], al[4];
                LDMX4(ah[0], ah[1], ah[2], ah[3], aH + ao);
                LDMX4(al[0], al[1], al[2], al[3], aL + ao);
#pragma unroll
                for (int ni = 0; ni < 4; ni++) {
                    const int bi = (ni >> 1) * 4 + (ni & 1) * 2;
                    MMA16816(c[mi][ni], ah, bh[bi], bh[bi + 1]);
                    MMA16816(c[mi][ni], ah, bl[bi], bl[bi + 1]);
                    MMA16816(c[mi][ni], al, bh[bi], bh[bi + 1]);
                }
            }
        }
        // no bottom sync: next iter's top sync orders compute(kt) before the
        // prefetch that overwrites this buffer.
    }

    const int lr = lane >> 2;
    const int lc = (lane & 3) * 2;
#pragma unroll
    for (int mi = 0; mi < 4; mi++) {
#pragma unroll
        for (int ni = 0; ni < 4; ni++) {
            const int gm = m0 + base_m + mi * 16 + lr;
            const int gn = n0 + base_n + ni * 8 + lc;
            float2 bv = *(const float2*)(bias + gn);
            float2 o0 = make_float2(c[mi][ni][0] + bv.x, c[mi][ni][1] + bv.y);
            float2 o1 = make_float2(c[mi][ni][2] + bv.x, c[mi][ni][3] + bv.y);
            if (MODE == 0) {
                __nv_bfloat16* Oh = (sel == 0) ? g_qsh : (sel == 1) ? g_ksh : g_vsh;
                __nv_bfloat16* Ol = (sel == 0) ? g_qsl : (sel == 1) ? g_ksl : g_vsl;
                const int h = gn >> 6, dk = gn & 63;
                uint32_t hi, lo;
                {
                    const int b = gm >> 10, s = gm & 1023;
                    const size_t idx = (((size_t)(b * NH + h)) * SEQL + s) * DK + dk;
                    split2(o0.x, o0.y, hi, lo);
                    *(uint32_t*)(Oh + idx) = hi;
                    *(uint32_t*)(Ol + idx) = lo;
                }
                {
                    const int m2 = gm + 8;
                    const int b = m2 >> 10, s = m2 & 1023;
                    const size_t idx = (((size_t)(b * NH + h)) * SEQL + s) * DK + dk;
                    split2(o1.x, o1.y, hi, lo);
                    *(uint32_t*)(Oh + idx) = hi;
                    *(uint32_t*)(Ol + idx) = lo;
                }
            } else {
                *(float2*)&OutPlain[(size_t)gm * DM + gn] = o0;
                *(float2*)&OutPlain[(size_t)(gm + 8) * DM + gn] = o1;
            }
        }
    }
}

// ---------------------------------------------------------------------------
// Flash attention: fused scores + softmax + P@V. One block = (z, 128 Q rows).
// 8 warps x 16 rows. K/V double-buffered cp.async. One sync per KV-iter.
// Epilogue writes ctx split bf16 into g_ah/g_al slot 0 (plain layout).
// ---------------------------------------------------------------------------
#define FLD 72
#define FTB (128 * FLD * 2)
#define F_QH 0
#define F_QL FTB
#define F_KH (2 * FTB)
#define F_KL (4 * FTB)
#define F_VH (6 * FTB)
#define F_VL (8 * FTB)
#define F_SMEM (10 * FTB)            // 184320 B

__global__ __launch_bounds__(256) void flash_mma(const int* __restrict__ mask)
{
    extern __shared__ char sm[];
    const uint32_t smb = smem_u32(sm);

    const int tid  = threadIdx.x;
    const int wid  = tid >> 5;
    const int lane = tid & 31;
    const int m0 = blockIdx.x * 128;
    const int z  = blockIdx.y;
    const int b  = z >> 4, h = z & 15;

    const __nv_bfloat16* Qh = g_qsh + (size_t)z * SEQL * DK;
    const __nv_bfloat16* Ql = g_qsl + (size_t)z * SEQL * DK;
    const __nv_bfloat16* Kh = g_ksh + (size_t)z * SEQL * DK;
    const __nv_bfloat16* Kl = g_ksl + (size_t)z * SEQL * DK;
    const __nv_bfloat16* Vh = g_vsh + (size_t)z * SEQL * DK;
    const __nv_bfloat16* Vl = g_vsl + (size_t)z * SEQL * DK;
    const int* __restrict__ M = mask + (size_t)b * SEQL * SEQL;

    const int trow = tid >> 1;
    const int tcb  = (tid & 1) * 32;

    const uint32_t a_lane = (uint32_t)(((lane & 15) * FLD + (lane >> 4) * 8) * 2);
    const uint32_t b_lane = (uint32_t)(((((lane >> 4) & 1) * 8 + (lane & 7)) * FLD
                                        + ((lane >> 3) & 1) * 8) * 2);
    const uint32_t t_lane = (uint32_t)(((lane & 15) * FLD + (lane >> 4) * 8) * 2);

    auto prefetchKV = [&](int kt, int st) {
        const uint32_t kH = smb + F_KH + st * FTB;
        const uint32_t kL = smb + F_KL + st * FTB;
        const uint32_t vH = smb + F_VH + st * FTB;
        const uint32_t vL = smb + F_VL + st * FTB;
#pragma unroll
        for (int i = 0; i < 4; i++) {
            const int col = tcb + i * 8;
            const uint32_t so = (uint32_t)(trow * (FLD * 2) + col * 2);
            const size_t go = (size_t)(kt * 128 + trow) * DK + col;
            CP16(kH + so, Kh + go);
            CP16(kL + so, Kl + go);
            CP16(vH + so, Vh + go);
            CP16(vL + so, Vl + go);
        }
    };

    {
#pragma unroll
        for (int i = 0; i < 4; i++) {
            const int col = tcb + i * 8;
            const uint32_t so = (uint32_t)(trow * (FLD * 2) + col * 2);
            const size_t go = (size_t)(m0 + trow) * DK + col;
            CP16(smb + F_QH + so, Qh + go);
            CP16(smb + F_QL + so, Ql + go);
        }
    }
    CP_COMMIT();
    prefetchKV(0, 0);
    CP_COMMIT();

    CP_WAIT1();          // Q ready
    __syncthreads();

    uint32_t qfh[4][4], qfl[4][4];
#pragma unroll
    for (int ks = 0; ks < 4; ks++) {
        const uint32_t ao = (uint32_t)(wid * 16 * (FLD * 2) + ks * 32) + a_lane;
        LDMX4(qfh[ks][0], qfh[ks][1], qfh[ks][2], qfh[ks][3], smb + F_QH + ao);
        LDMX4(qfl[ks][0], qfl[ks][1], qfl[ks][2], qfl[ks][3], smb + F_QL + ao);
    }

    const int gr = lane >> 2;
    const int lc = (lane & 3) * 2;
    const int r0 = m0 + wid * 16 + gr;
    const int r1 = r0 + 8;

    float m0s = -1e30f, m1s = -1e30f;
    float l0 = 0.f, l1 = 0.f;
    float co[8][4];
#pragma unroll
    for (int j = 0; j < 8; j++)
#pragma unroll
        for (int r = 0; r < 4; r++) co[j][r] = 0.f;

    for (int kt = 0; kt < 8; kt++) {
        const int cur = kt & 1;
        CP_WAIT0();
        __syncthreads();
        if (kt < 7) { prefetchKV(kt + 1, cur ^ 1); CP_COMMIT(); }

        const uint32_t kH = smb + F_KH + cur * FTB;
        const uint32_t kL = smb + F_KL + cur * FTB;
        const uint32_t vH = smb + F_VH + cur * FTB;
        const uint32_t vL = smb + F_VL + cur * FTB;

        // ---- S = Q @ K^T (3-MMA split) ----
        float cs[16][4];
#pragma unroll
        for (int j = 0; j < 16; j++)
#pragma unroll
            for (int r = 0; r < 4; r++) cs[j][r] = 0.f;

#pragma unroll
        for (int ks = 0; ks < 4; ks++) {
#pragma unroll
            for (int ni2 = 0; ni2 < 8; ni2++) {
                const uint32_t bo = (uint32_t)(ni2 * 16 * (FLD * 2) + ks * 32) + b_lane;
                uint32_t bh0, bh1, bh2, bh3, bl0, bl1, bl2, bl3;
                LDMX4(bh0, bh1, bh2, bh3, kH + bo);
                LDMX4(bl0, bl1, bl2, bl3, kL + bo);
                const int j0 = 2 * ni2;
                MMA16816(cs[j0], qfh[ks], bh0, bh1);
                MMA16816(cs[j0], qfh[ks], bl0, bl1);
                MMA16816(cs[j0], qfl[ks], bh0, bh1);
                MMA16816(cs[j0 + 1], qfh[ks], bh2, bh3);
                MMA16816(cs[j0 + 1], qfh[ks], bl2, bl3);
                MMA16816(cs[j0 + 1], qfl[ks], bh2, bh3);
            }
        }

        // ---- scale + mask ----
        const int n0 = kt * 128;
#pragma unroll
        for (int j = 0; j < 16; j++) {
            const int col = n0 + 8 * j + lc;
            int2 mk0 = *(const int2*)&M[(size_t)r0 * SEQL + col];
            int2 mk1 = *(const int2*)&M[(size_t)r1 * SEQL + col];
            cs[j][0] = mk0.x ? cs[j][0] * 0.125f : -1e9f;
            cs[j][1] = mk0.y ? cs[j][1] * 0.125f : -1e9f;
            cs[j][2] = mk1.x ? cs[j][2] * 0.125f : -1e9f;
            cs[j][3] = mk1.y ? cs[j][3] * 0.125f : -1e9f;
        }

        // ---- online softmax ----
        float mx0 = -1e30f, mx1 = -1e30f;
#pragma unroll
        for (int j = 0; j < 16; j++) {
            mx0 = fmaxf(mx0, fmaxf(cs[j][0], cs[j][1]));
            mx1 = fmaxf(mx1, fmaxf(cs[j][2], cs[j][3]));
        }
        mx0 = fmaxf(mx0, __shfl_xor_sync(0xffffffffu, mx0, 1));
        mx0 = fmaxf(mx0, __shfl_xor_sync(0xffffffffu, mx0, 2));
        mx1 = fmaxf(mx1, __shfl_xor_sync(0xffffffffu, mx1, 1));
        mx1 = fmaxf(mx1, __shfl_xor_sync(0xffffffffu, mx1, 2));

        const float mn0 = fmaxf(m0s, mx0);
        const float mn1 = fmaxf(m1s, mx1);
        const float a0 = __expf(m0s - mn0);
        const float a1 = __expf(m1s - mn1);
        m0s = mn0; m1s = mn1;

        float s0 = 0.f, s1 = 0.f;
#pragma unroll
        for (int j = 0; j < 16; j++) {
            float e0 = __expf(cs[j][0] - mn0);
            float e1 = __expf(cs[j][1] - mn0);
            float e2 = __expf(cs[j][2] - mn1);
            float e3 = __expf(cs[j][3] - mn1);
            cs[j][0] = e0; cs[j][1] = e1; cs[j][2] = e2; cs[j][3] = e3;
            s0 += e0 + e1; s1 += e2 + e3;
        }
        s0 += __shfl_xor_sync(0xffffffffu, s0, 1);
        s0 += __shfl_xor_sync(0xffffffffu, s0, 2);
        s1 += __shfl_xor_sync(0xffffffffu, s1, 1);
        s1 += __shfl_xor_sync(0xffffffffu, s1, 2);
        l0 = l0 * a0 + s0;
        l1 = l1 * a1 + s1;

#pragma unroll
        for (int j = 0; j < 8; j++) {
            co[j][0] *= a0; co[j][1] *= a0;
            co[j][2] *= a1; co[j][3] *= a1;
        }

        // ---- pack P: C-frag pairs -> A-frags (hi/lo) ----
        uint32_t ph[8][4], pl[8][4];
#pragma unroll
        for (int ks = 0; ks < 8; ks++) {
            const int j = 2 * ks;
            split2(cs[j][0], cs[j][1], ph[ks][0], pl[ks][0]);
            split2(cs[j][2], cs[j][3], ph[ks][1], pl[ks][1]);
            split2(cs[j + 1][0], cs[j + 1][1], ph[ks][2], pl[ks][2]);
            split2(cs[j + 1][2], cs[j + 1][3], ph[ks][3], pl[ks][3]);
        }

        // ---- O += P @ V (3-MMA split), V via ldmatrix.trans ----
#pragma unroll
        for (int ks = 0; ks < 8; ks++) {
#pragma unroll
            for (int nt = 0; nt < 4; nt++) {
                const uint32_t bo = (uint32_t)(ks * 16 * (FLD * 2) + nt * 16 * 2) + t_lane;
                uint32_t vh0, vh1, vh2, vh3, vl0, vl1, vl2, vl3;
                LDMX4T(vh0, vh1, vh2, vh3, vH + bo);
                LDMX4T(vl0, vl1, vl2, vl3, vL + bo);
                const int j0 = 2 * nt;
                MMA16816(co[j0], ph[ks], vh0, vh1);
                MMA16816(co[j0], ph[ks], vl0, vl1);
                MMA16816(co[j0], pl[ks], vh0, vh1);
                MMA16816(co[j0 + 1], ph[ks], vh2, vh3);
                MMA16816(co[j0 + 1], ph[ks], vl2, vl3);
                MMA16816(co[j0 + 1], pl[ks], vh2, vh3);
            }
        }
        // no bottom sync: next iter's top sync protects buffer reuse.
    }

    // ---- epilogue: O /= l, split bf16, write into A slot 0 ----
    const float inv0 = 1.f / l0;
    const float inv1 = 1.f / l1;
#pragma unroll
    for (int j = 0; j < 8; j++) {
        const int col = h * 64 + 8 * j + lc;
        uint32_t hi, lo;
        split2(co[j][0] * inv0, co[j][1] * inv0, hi, lo);
        {
            const size_t o = (size_t)(b * SEQL + r0) * DM + col;
            *(uint32_t*)(g_ah + o) = hi;
            *(uint32_t*)(g_al + o) = lo;
        }
        split2(co[j][2] * inv1, co[j][3] * inv1, hi, lo);
        {
            const size_t o = (size_t)(b * SEQL + r1) * DM + col;
            *(uint32_t*)(g_ah + o) = hi;
            *(uint32_t*)(g_al + o) = lo;
        }
    }
}

// ===========================================================================
extern "C" void kernel_launch(void* const* d_in, const int* in_sizes, int n_in,
                              void* d_out, int out_size)
{
    const float* q    = (const float*)d_in[0];
    const float* k    = (const float*)d_in[1];
    const float* v    = (const float*)d_in[2];
    const int*   mask = (const int*)  d_in[3];
    const float* Wq   = (const float*)d_in[4];
    const float* bq   = (const float*)d_in[5];
    const float* Wk   = (const float*)d_in[6];
    const float* bk   = (const float*)d_in[7];
    const float* Wv   = (const float*)d_in[8];
    const float* bv   = (const float*)d_in[9];
    const float* Wo   = (const float*)d_in[10];
    const float* bo   = (const float*)d_in[11];
    float* out = (float*)d_out;

    cudaFuncSetAttribute(mma_gemm<0>, cudaFuncAttributeMaxDynamicSharedMemorySize, G_SMEM);
    cudaFuncSetAttribute(mma_gemm<1>, cudaFuncAttributeMaxDynamicSharedMemorySize, G_SMEM);
    cudaFuncSetAttribute(flash_mma,   cudaFuncAttributeMaxDynamicSharedMemorySize, F_SMEM);

    dim3 gb(256);

    // glue: one split launch, one transpose launch
    dim3 gSplit((BSZ * SEQL * DM) / 4 / 256, 3);       // (8192, 3)
    split_qkv_kernel<<<gSplit, gb>>>(q, k, v);
    dim3 tb(32, 8);
    dim3 tg(DM / 32, DM / 32, 4);
    transpose4_kernel<<<tg, tb>>>(Wq, Wk, Wv, Wo);

    // merged Q/K/V projection GEMMs
    dim3 gg(DM / 128, (BSZ * SEQL) / 128, 3);          // (8, 64, 3)
    mma_gemm<0><<<gg, gb, G_SMEM>>>(bq, bk, bv, nullptr);

    // fused attention
    dim3 gF(SEQL / 128, ZTOT);                         // (8, 128)
    flash_mma<<<gF, gb, F_SMEM>>>(mask);

    // output projection
    dim3 go(DM / 128, (BSZ * SEQL) / 128, 1);
    mma_gemm<1><<<go, gb, G_SMEM>>>(bo, nullptr, nullptr, out);
}

// round 17
// speedup vs baseline: 3.0115x; 1.0856x over previous
#include <cuda_runtime.h>
#include <cuda_bf16.h>
#include <cstdint>

#define BSZ 8
#define NH 16
#define SEQL 1024
#define DM 1024
#define DK 64
#define ZTOT (BSZ*NH)

#define ASZ ((size_t)BSZ*SEQL*DM)     // 8M elems per A slot
#define WSZ ((size_t)DM*DM)           // 1M elems per W slot

// ---------------------------------------------------------------------------
// Device scratch (static — no allocation)
// ---------------------------------------------------------------------------
static __device__ __align__(16) __nv_bfloat16 g_qsh[(size_t)ZTOT*SEQL*DK];
static __device__ __align__(16) __nv_bfloat16 g_qsl[(size_t)ZTOT*SEQL*DK];
static __device__ __align__(16) __nv_bfloat16 g_ksh[(size_t)ZTOT*SEQL*DK];
static __device__ __align__(16) __nv_bfloat16 g_ksl[(size_t)ZTOT*SEQL*DK];
static __device__ __align__(16) __nv_bfloat16 g_vsh[(size_t)ZTOT*SEQL*DK];
static __device__ __align__(16) __nv_bfloat16 g_vsl[(size_t)ZTOT*SEQL*DK];
static __device__ __align__(16) __nv_bfloat16 g_ah [3*ASZ];   // A hi: slots q,k,v (slot 0 reused for ctx)
static __device__ __align__(16) __nv_bfloat16 g_al [3*ASZ];   // A lo
static __device__ __align__(16) __nv_bfloat16 g_bh [4*WSZ];   // W^T hi
static __device__ __align__(16) __nv_bfloat16 g_bl [4*WSZ];   // W^T lo
static __device__ __align__(16) uint32_t g_mask[(size_t)BSZ*SEQL*(SEQL/32)];  // 1 bit per mask elem

// ---------------------------------------------------------------------------
// helpers
// ---------------------------------------------------------------------------
__device__ __forceinline__ uint32_t smem_u32(const void* p) {
    uint32_t a;
    asm("{ .reg .u64 t; cvta.to.shared.u64 t, %1; cvt.u32.u64 %0, t; }" : "=r"(a) : "l"(p));
    return a;
}

#define LDMX4(r0, r1, r2, r3, addr) \
    asm volatile("ldmatrix.sync.aligned.m8n8.x4.shared.b16 {%0,%1,%2,%3}, [%4];" \
        : "=r"(r0), "=r"(r1), "=r"(r2), "=r"(r3) : "r"(addr))

#define LDMX4T(r0, r1, r2, r3, addr) \
    asm volatile("ldmatrix.sync.aligned.m8n8.x4.trans.shared.b16 {%0,%1,%2,%3}, [%4];" \
        : "=r"(r0), "=r"(r1), "=r"(r2), "=r"(r3) : "r"(addr))

#define MMA16816(c, a, b0, b1) \
    asm volatile("mma.sync.aligned.m16n8k16.row.col.f32.bf16.bf16.f32 " \
        "{%0,%1,%2,%3}, {%4,%5,%6,%7}, {%8,%9}, {%0,%1,%2,%3};" \
        : "+f"((c)[0]), "+f"((c)[1]), "+f"((c)[2]), "+f"((c)[3]) \
        : "r"((a)[0]), "r"((a)[1]), "r"((a)[2]), "r"((a)[3]), "r"(b0), "r"(b1))

#define CP16(saddr, gptr) \
    asm volatile("cp.async.cg.shared.global [%0], [%1], 16;" :: "r"((uint32_t)(saddr)), "l"(gptr))
#define CP_COMMIT() asm volatile("cp.async.commit_group;" ::: "memory")
#define CP_WAIT0()  asm volatile("cp.async.wait_group 0;" ::: "memory")
#define CP_WAIT1()  asm volatile("cp.async.wait_group 1;" ::: "memory")

__device__ __forceinline__ void split2(float x, float y, uint32_t& hi, uint32_t& lo) {
    __nv_bfloat16 hx = __float2bfloat16_rn(x);
    __nv_bfloat16 hy = __float2bfloat16_rn(y);
    __nv_bfloat162 hp(hx, hy);
    __nv_bfloat162 lp = __floats2bfloat162_rn(x - __bfloat162float(hx),
                                              y - __bfloat162float(hy));
    hi = *(uint32_t*)&hp;
    lo = *(uint32_t*)&lp;
}

// ---------------------------------------------------------------------------
// merged input split: q,k,v fp32 -> g_ah/g_al slots 0,1,2
// ---------------------------------------------------------------------------
__global__ __launch_bounds__(256) void split_qkv_kernel(
    const float* __restrict__ q, const float* __restrict__ k, const float* __restrict__ v)
{
    const int z = blockIdx.y;
    const float* src = (z == 0) ? q : (z == 1) ? k : v;
    const size_t i4 = (size_t)blockIdx.x * 256 + threadIdx.x;
    float4 x = *(const float4*)(src + i4 * 4);
    uint32_t h0, l0, h1, l1;
    split2(x.x, x.y, h0, l0);
    split2(x.z, x.w, h1, l1);
    *(uint2*)(g_ah + z * ASZ + i4 * 4) = make_uint2(h0, h1);
    *(uint2*)(g_al + z * ASZ + i4 * 4) = make_uint2(l0, l1);
}

// ---------------------------------------------------------------------------
// merged weight transpose + split: 4 weights -> g_bh/g_bl slots 0..3
// ---------------------------------------------------------------------------
__global__ __launch_bounds__(256) void transpose4_kernel(
    const float* __restrict__ Wq, const float* __restrict__ Wk,
    const float* __restrict__ Wv, const float* __restrict__ Wo)
{
    __shared__ float t[32][33];
    const int z = blockIdx.z;
    const float* W = (z == 0) ? Wq : (z == 1) ? Wk : (z == 2) ? Wv : Wo;
    const int bx = blockIdx.x * 32, by = blockIdx.y * 32;
    const int tx = threadIdx.x, ty = threadIdx.y;  // 32x8
#pragma unroll
    for (int j = 0; j < 32; j += 8)
        t[ty + j][tx] = W[(size_t)(by + ty + j) * DM + bx + tx];
    __syncthreads();
#pragma unroll
    for (int j = 0; j < 32; j += 8) {
        float x = t[tx][ty + j];
        __nv_bfloat16 h = __float2bfloat16_rn(x);
        __nv_bfloat16 l = __float2bfloat16_rn(x - __bfloat162float(h));
        const size_t o = z * WSZ + (size_t)(bx + ty + j) * DM + by + tx;
        g_bh[o] = h;
        g_bl[o] = l;
    }
}

// ---------------------------------------------------------------------------
// mask bit-pack: int32 0/1 [b][s][s] -> 1 bit each, uint32 words
// one thread packs 32 ints (8 x int4)
// ---------------------------------------------------------------------------
__global__ __launch_bounds__(256) void pack_mask_kernel(const int* __restrict__ M)
{
    const size_t w = (size_t)blockIdx.x * 256 + threadIdx.x;
    const int4* p = (const int4*)(M + w * 32);
    uint32_t bits = 0;
#pragma unroll
    for (int i = 0; i < 8; i++) {
        int4 v = p[i];
        bits |= (v.x ? 1u : 0u) << (i * 4 + 0);
        bits |= (v.y ? 1u : 0u) << (i * 4 + 1);
        bits |= (v.z ? 1u : 0u) << (i * 4 + 2);
        bits |= (v.w ? 1u : 0u) << (i * 4 + 3);
    }
    g_mask[w] = bits;
}

// ---------------------------------------------------------------------------
// GEMM, 2-stage cp.async pipelined, bf16 3-MMA split, 2 CTAs/SM.
// MODE 0: grid.z = 3 (q/k/v); MODE 1: ctx @ Wo -> fp32 OutPlain.
// ---------------------------------------------------------------------------
#define LDA 40
#define GT  (128 * LDA * 2)
#define G_SMEM (8 * GT)

template <int MODE>
__global__ __launch_bounds__(256, 2) void mma_gemm(
    const float* __restrict__ bias0, const float* __restrict__ bias1,
    const float* __restrict__ bias2, float* __restrict__ OutPlain)
{
    extern __shared__ char sm[];
    const uint32_t smb = smem_u32(sm);

    const int tid  = threadIdx.x;
    const int wid  = tid >> 5;
    const int lane = tid & 31;
    const int m0 = blockIdx.y * 128;
    const int n0 = blockIdx.x * 128;
    const int sel = (MODE == 0) ? blockIdx.z : 0;
    const int bslot = (MODE == 0) ? sel : 3;
    const __nv_bfloat16* __restrict__ Ah = g_ah + (size_t)sel * ASZ;
    const __nv_bfloat16* __restrict__ Al = g_al + (size_t)sel * ASZ;
    const __nv_bfloat16* __restrict__ Bh = g_bh + (size_t)bslot * WSZ;
    const __nv_bfloat16* __restrict__ Bl = g_bl + (size_t)bslot * WSZ;
    const float* __restrict__ bias =
        (MODE == 1) ? bias0 : (sel == 0) ? bias0 : (sel == 1) ? bias1 : bias2;

    const int base_m = (wid >> 2) * 64;
    const int base_n = (wid & 3) * 32;
    const int grow = tid >> 2;
    const int gch  = (tid & 3) * 8;

    const uint32_t a_lane = (uint32_t)(((lane & 15) * LDA + (lane >> 4) * 8) * 2);
    const uint32_t b_lane = (uint32_t)(((((lane >> 4) & 1) * 8 + (lane & 7)) * LDA
                                        + ((lane >> 3) & 1) * 8) * 2);

    const uint32_t so0 = (uint32_t)(grow * (LDA * 2) + gch * 2);
    const uint32_t so1 = so0 + 64 * (LDA * 2);

    float c[4][4][4];
#pragma unroll
    for (int i = 0; i < 4; i++)
#pragma unroll
        for (int j = 0; j < 4; j++)
#pragma unroll
            for (int r = 0; r < 4; r++) c[i][j][r] = 0.f;

    auto prefetch = [&](int kt, int st) {
        const size_t a0 = (size_t)(m0 + grow) * DM + kt * 32 + gch;
        const size_t b0 = (size_t)(n0 + grow) * DM + kt * 32 + gch;
        const uint32_t aH = smb + 0 * GT * 2 + st * GT;
        const uint32_t aL = smb + 1 * GT * 2 + st * GT;
        const uint32_t bH = smb + 2 * GT * 2 + st * GT;
        const uint32_t bL = smb + 3 * GT * 2 + st * GT;
        CP16(aH + so0, Ah + a0); CP16(aH + so1, Ah + a0 + (size_t)64 * DM);
        CP16(aL + so0, Al + a0); CP16(aL + so1, Al + a0 + (size_t)64 * DM);
        CP16(bH + so0, Bh + b0); CP16(bH + so1, Bh + b0 + (size_t)64 * DM);
        CP16(bL + so0, Bl + b0); CP16(bL + so1, Bl + b0 + (size_t)64 * DM);
    };

    prefetch(0, 0);
    CP_COMMIT();

    for (int kt = 0; kt < 32; kt++) {
        const int cur = kt & 1;
        CP_WAIT0();
        __syncthreads();
        if (kt < 31) { prefetch(kt + 1, cur ^ 1); CP_COMMIT(); }

        const uint32_t aH = smb + 0 * GT * 2 + cur * GT;
        const uint32_t aL = smb + 1 * GT * 2 + cur * GT;
        const uint32_t bH = smb + 2 * GT * 2 + cur * GT;
        const uint32_t bL = smb + 3 * GT * 2 + cur * GT;

#pragma unroll
        for (int ks = 0; ks < 2; ks++) {
            uint32_t bh[8], bl[8];
#pragma unroll
            for (int ni2 = 0; ni2 < 2; ni2++) {
                const uint32_t bo = (uint32_t)((base_n + ni2 * 16) * (LDA * 2) + ks * 32) + b_lane;
                LDMX4(bh[ni2*4+0], bh[ni2*4+1], bh[ni2*4+2], bh[ni2*4+3], bH + bo);
                LDMX4(bl[ni2*4+0], bl[ni2*4+1], bl[ni2*4+2], bl[ni2*4+3], bL + bo);
            }
#pragma unroll
            for (int mi = 0; mi < 4; mi++) {
                const uint32_t ao = (uint32_t)((base_m + mi * 16) * (LDA * 2) + ks * 32) + a_lane;
                uint32_t ah[4], al[4];
                LDMX4(ah[0], ah[1], ah[2], ah[3], aH + ao);
                LDMX4(al[0], al[1], al[2], al[3], aL + ao);
#pragma unroll
                for (int ni = 0; ni < 4; ni++) {
                    const int bi = (ni >> 1) * 4 + (ni & 1) * 2;
                    MMA16816(c[mi][ni], ah, bh[bi], bh[bi + 1]);
                    MMA16816(c[mi][ni], ah, bl[bi], bl[bi + 1]);
                    MMA16816(c[mi][ni], al, bh[bi], bh[bi + 1]);
                }
            }
        }
    }

    const int lr = lane >> 2;
    const int lc = (lane & 3) * 2;
#pragma unroll
    for (int mi = 0; mi < 4; mi++) {
#pragma unroll
        for (int ni = 0; ni < 4; ni++) {
            const int gm = m0 + base_m + mi * 16 + lr;
            const int gn = n0 + base_n + ni * 8 + lc;
            float2 bv = *(const float2*)(bias + gn);
            float2 o0 = make_float2(c[mi][ni][0] + bv.x, c[mi][ni][1] + bv.y);
            float2 o1 = make_float2(c[mi][ni][2] + bv.x, c[mi][ni][3] + bv.y);
            if (MODE == 0) {
                __nv_bfloat16* Oh = (sel == 0) ? g_qsh : (sel == 1) ? g_ksh : g_vsh;
                __nv_bfloat16* Ol = (sel == 0) ? g_qsl : (sel == 1) ? g_ksl : g_vsl;
                const int h = gn >> 6, dk = gn & 63;
                uint32_t hi, lo;
                {
                    const int b = gm >> 10, s = gm & 1023;
                    const size_t idx = (((size_t)(b * NH + h)) * SEQL + s) * DK + dk;
                    split2(o0.x, o0.y, hi, lo);
                    *(uint32_t*)(Oh + idx) = hi;
                    *(uint32_t*)(Ol + idx) = lo;
                }
                {
                    const int m2 = gm + 8;
                    const int b = m2 >> 10, s = m2 & 1023;
                    const size_t idx = (((size_t)(b * NH + h)) * SEQL + s) * DK + dk;
                    split2(o1.x, o1.y, hi, lo);
                    *(uint32_t*)(Oh + idx) = hi;
                    *(uint32_t*)(Ol + idx) = lo;
                }
            } else {
                *(float2*)&OutPlain[(size_t)gm * DM + gn] = o0;
                *(float2*)&OutPlain[(size_t)(gm + 8) * DM + gn] = o1;
            }
        }
    }
}

// ---------------------------------------------------------------------------
// Flash attention with bit-packed mask. One block = (z, 128 Q rows), 8 warps.
// ---------------------------------------------------------------------------
#define FLD 72
#define FTB (128 * FLD * 2)
#define F_QH 0
#define F_QL FTB
#define F_KH (2 * FTB)
#define F_KL (4 * FTB)
#define F_VH (6 * FTB)
#define F_VL (8 * FTB)
#define F_SMEM (10 * FTB)            // 184320 B

__global__ __launch_bounds__(256) void flash_mma()
{
    extern __shared__ char sm[];
    const uint32_t smb = smem_u32(sm);

    const int tid  = threadIdx.x;
    const int wid  = tid >> 5;
    const int lane = tid & 31;
    const int m0 = blockIdx.x * 128;
    const int z  = blockIdx.y;
    const int b  = z >> 4, h = z & 15;

    const __nv_bfloat16* Qh = g_qsh + (size_t)z * SEQL * DK;
    const __nv_bfloat16* Ql = g_qsl + (size_t)z * SEQL * DK;
    const __nv_bfloat16* Kh = g_ksh + (size_t)z * SEQL * DK;
    const __nv_bfloat16* Kl = g_ksl + (size_t)z * SEQL * DK;
    const __nv_bfloat16* Vh = g_vsh + (size_t)z * SEQL * DK;
    const __nv_bfloat16* Vl = g_vsl + (size_t)z * SEQL * DK;

    const int trow = tid >> 1;
    const int tcb  = (tid & 1) * 32;

    const uint32_t a_lane = (uint32_t)(((lane & 15) * FLD + (lane >> 4) * 8) * 2);
    const uint32_t b_lane = (uint32_t)(((((lane >> 4) & 1) * 8 + (lane & 7)) * FLD
                                        + ((lane >> 3) & 1) * 8) * 2);
    const uint32_t t_lane = (uint32_t)(((lane & 15) * FLD + (lane >> 4) * 8) * 2);

    auto prefetchKV = [&](int kt, int st) {
        const uint32_t kH = smb + F_KH + st * FTB;
        const uint32_t kL = smb + F_KL + st * FTB;
        const uint32_t vH = smb + F_VH + st * FTB;
        const uint32_t vL = smb + F_VL + st * FTB;
#pragma unroll
        for (int i = 0; i < 4; i++) {
            const int col = tcb + i * 8;
            const uint32_t so = (uint32_t)(trow * (FLD * 2) + col * 2);
            const size_t go = (size_t)(kt * 128 + trow) * DK + col;
            CP16(kH + so, Kh + go);
            CP16(kL + so, Kl + go);
            CP16(vH + so, Vh + go);
            CP16(vL + so, Vl + go);
        }
    };

    {
#pragma unroll
        for (int i = 0; i < 4; i++) {
            const int col = tcb + i * 8;
            const uint32_t so = (uint32_t)(trow * (FLD * 2) + col * 2);
            const size_t go = (size_t)(m0 + trow) * DK + col;
            CP16(smb + F_QH + so, Qh + go);
            CP16(smb + F_QL + so, Ql + go);
        }
    }
    CP_COMMIT();
    prefetchKV(0, 0);
    CP_COMMIT();

    CP_WAIT1();          // Q ready
    __syncthreads();

    uint32_t qfh[4][4], qfl[4][4];
#pragma unroll
    for (int ks = 0; ks < 4; ks++) {
        const uint32_t ao = (uint32_t)(wid * 16 * (FLD * 2) + ks * 32) + a_lane;
        LDMX4(qfh[ks][0], qfh[ks][1], qfh[ks][2], qfh[ks][3], smb + F_QH + ao);
        LDMX4(qfl[ks][0], qfl[ks][1], qfl[ks][2], qfl[ks][3], smb + F_QL + ao);
    }

    const int gr = lane >> 2;
    const int lc = (lane & 3) * 2;
    const int r0 = m0 + wid * 16 + gr;
    const int r1 = r0 + 8;

    // packed mask row pointers (b-dependent only)
    const uint32_t* __restrict__ Mw0 = g_mask + ((size_t)b * SEQL + r0) * (SEQL / 32);
    const uint32_t* __restrict__ Mw1 = g_mask + ((size_t)b * SEQL + r1) * (SEQL / 32);

    float m0s = -1e30f, m1s = -1e30f;
    float l0 = 0.f, l1 = 0.f;
    float co[8][4];
#pragma unroll
    for (int j = 0; j < 8; j++)
#pragma unroll
        for (int r = 0; r < 4; r++) co[j][r] = 0.f;

    for (int kt = 0; kt < 8; kt++) {
        const int cur = kt & 1;

        // mask words for this 128-col tile — issue early, consumed after S MMAs
        uint4 wm0 = *(const uint4*)(Mw0 + kt * 4);
        uint4 wm1 = *(const uint4*)(Mw1 + kt * 4);

        CP_WAIT0();
        __syncthreads();
        if (kt < 7) { prefetchKV(kt + 1, cur ^ 1); CP_COMMIT(); }

        const uint32_t kH = smb + F_KH + cur * FTB;
        const uint32_t kL = smb + F_KL + cur * FTB;
        const uint32_t vH = smb + F_VH + cur * FTB;
        const uint32_t vL = smb + F_VL + cur * FTB;

        // ---- S = Q @ K^T (3-MMA split) ----
        float cs[16][4];
#pragma unroll
        for (int j = 0; j < 16; j++)
#pragma unroll
            for (int r = 0; r < 4; r++) cs[j][r] = 0.f;

#pragma unroll
        for (int ks = 0; ks < 4; ks++) {
#pragma unroll
            for (int ni2 = 0; ni2 < 8; ni2++) {
                const uint32_t bo = (uint32_t)(ni2 * 16 * (FLD * 2) + ks * 32) + b_lane;
                uint32_t bh0, bh1, bh2, bh3, bl0, bl1, bl2, bl3;
                LDMX4(bh0, bh1, bh2, bh3, kH + bo);
                LDMX4(bl0, bl1, bl2, bl3, kL + bo);
                const int j0 = 2 * ni2;
                MMA16816(cs[j0], qfh[ks], bh0, bh1);
                MMA16816(cs[j0], qfh[ks], bl0, bl1);
                MMA16816(cs[j0], qfl[ks], bh0, bh1);
                MMA16816(cs[j0 + 1], qfh[ks], bh2, bh3);
                MMA16816(cs[j0 + 1], qfh[ks], bl2, bl3);
                MMA16816(cs[j0 + 1], qfl[ks], bh2, bh3);
            }
        }

        // ---- scale + mask via bit tests ----
        const uint32_t w0a[4] = {wm0.x, wm0.y, wm0.z, wm0.w};
        const uint32_t w1a[4] = {wm1.x, wm1.y, wm1.z, wm1.w};
#pragma unroll
        for (int j = 0; j < 16; j++) {
            const uint32_t wr0 = w0a[j >> 2];
            const uint32_t wr1 = w1a[j >> 2];
            const int bp = 8 * (j & 3) + lc;
            cs[j][0] = ((wr0 >> bp) & 1u) ? cs[j][0] * 0.125f : -1e9f;
            cs[j][1] = ((wr0 >> (bp + 1)) & 1u) ? cs[j][1] * 0.125f : -1e9f;
            cs[j][2] = ((wr1 >> bp) & 1u) ? cs[j][2] * 0.125f : -1e9f;
            cs[j][3] = ((wr1 >> (bp + 1)) & 1u) ? cs[j][3] * 0.125f : -1e9f;
        }

        // ---- online softmax ----
        float mx0 = -1e30f, mx1 = -1e30f;
#pragma unroll
        for (int j = 0; j < 16; j++) {
            mx0 = fmaxf(mx0, fmaxf(cs[j][0], cs[j][1]));
            mx1 = fmaxf(mx1, fmaxf(cs[j][2], cs[j][3]));
        }
        mx0 = fmaxf(mx0, __shfl_xor_sync(0xffffffffu, mx0, 1));
        mx0 = fmaxf(mx0, __shfl_xor_sync(0xffffffffu, mx0, 2));
        mx1 = fmaxf(mx1, __shfl_xor_sync(0xffffffffu, mx1, 1));
        mx1 = fmaxf(mx1, __shfl_xor_sync(0xffffffffu, mx1, 2));

        const float mn0 = fmaxf(m0s, mx0);
        const float mn1 = fmaxf(m1s, mx1);
        const float a0 = __expf(m0s - mn0);
        const float a1 = __expf(m1s - mn1);
        m0s = mn0; m1s = mn1;

        float s0 = 0.f, s1 = 0.f;
#pragma unroll
        for (int j = 0; j < 16; j++) {
            float e0 = __expf(cs[j][0] - mn0);
            float e1 = __expf(cs[j][1] - mn0);
            float e2 = __expf(cs[j][2] - mn1);
            float e3 = __expf(cs[j][3] - mn1);
            cs[j][0] = e0; cs[j][1] = e1; cs[j][2] = e2; cs[j][3] = e3;
            s0 += e0 + e1; s1 += e2 + e3;
        }
        s0 += __shfl_xor_sync(0xffffffffu, s0, 1);
        s0 += __shfl_xor_sync(0xffffffffu, s0, 2);
        s1 += __shfl_xor_sync(0xffffffffu, s1, 1);
        s1 += __shfl_xor_sync(0xffffffffu, s1, 2);
        l0 = l0 * a0 + s0;
        l1 = l1 * a1 + s1;

#pragma unroll
        for (int j = 0; j < 8; j++) {
            co[j][0] *= a0; co[j][1] *= a0;
            co[j][2] *= a1; co[j][3] *= a1;
        }

        // ---- pack P: C-frag pairs -> A-frags (hi/lo) ----
        uint32_t ph[8][4], pl[8][4];
#pragma unroll
        for (int ks = 0; ks < 8; ks++) {
            const int j = 2 * ks;
            split2(cs[j][0], cs[j][1], ph[ks][0], pl[ks][0]);
            split2(cs[j][2], cs[j][3], ph[ks][1], pl[ks][1]);
            split2(cs[j + 1][0], cs[j + 1][1], ph[ks][2], pl[ks][2]);
            split2(cs[j + 1][2], cs[j + 1][3], ph[ks][3], pl[ks][3]);
        }

        // ---- O += P @ V (3-MMA split), V via ldmatrix.trans ----
#pragma unroll
        for (int ks = 0; ks < 8; ks++) {
#pragma unroll
            for (int nt = 0; nt < 4; nt++) {
                const uint32_t bo = (uint32_t)(ks * 16 * (FLD * 2) + nt * 16 * 2) + t_lane;
                uint32_t vh0, vh1, vh2, vh3, vl0, vl1, vl2, vl3;
                LDMX4T(vh0, vh1, vh2, vh3, vH + bo);
                LDMX4T(vl0, vl1, vl2, vl3, vL + bo);
                const int j0 = 2 * nt;
                MMA16816(co[j0], ph[ks], vh0, vh1);
                MMA16816(co[j0], ph[ks], vl0, vl1);
                MMA16816(co[j0], pl[ks], vh0, vh1);
                MMA16816(co[j0 + 1], ph[ks], vh2, vh3);
                MMA16816(co[j0 + 1], ph[ks], vl2, vl3);
                MMA16816(co[j0 + 1], pl[ks], vh2, vh3);
            }
        }
    }

    // ---- epilogue: O /= l, split bf16, write into A slot 0 ----
    const float inv0 = 1.f / l0;
    const float inv1 = 1.f / l1;
#pragma unroll
    for (int j = 0; j < 8; j++) {
        const int col = h * 64 + 8 * j + lc;
        uint32_t hi, lo;
        split2(co[j][0] * inv0, co[j][1] * inv0, hi, lo);
        {
            const size_t o = (size_t)(b * SEQL + r0) * DM + col;
            *(uint32_t*)(g_ah + o) = hi;
            *(uint32_t*)(g_al + o) = lo;
        }
        split2(co[j][2] * inv1, co[j][3] * inv1, hi, lo);
        {
            const size_t o = (size_t)(b * SEQL + r1) * DM + col;
            *(uint32_t*)(g_ah + o) = hi;
            *(uint32_t*)(g_al + o) = lo;
        }
    }
}

// ===========================================================================
extern "C" void kernel_launch(void* const* d_in, const int* in_sizes, int n_in,
                              void* d_out, int out_size)
{
    const float* q    = (const float*)d_in[0];
    const float* k    = (const float*)d_in[1];
    const float* v    = (const float*)d_in[2];
    const int*   mask = (const int*)  d_in[3];
    const float* Wq   = (const float*)d_in[4];
    const float* bq   = (const float*)d_in[5];
    const float* Wk   = (const float*)d_in[6];
    const float* bk   = (const float*)d_in[7];
    const float* Wv   = (const float*)d_in[8];
    const float* bv   = (const float*)d_in[9];
    const float* Wo   = (const float*)d_in[10];
    const float* bo   = (const float*)d_in[11];
    float* out = (float*)d_out;

    cudaFuncSetAttribute(mma_gemm<0>, cudaFuncAttributeMaxDynamicSharedMemorySize, G_SMEM);
    cudaFuncSetAttribute(mma_gemm<1>, cudaFuncAttributeMaxDynamicSharedMemorySize, G_SMEM);
    cudaFuncSetAttribute(flash_mma,   cudaFuncAttributeMaxDynamicSharedMemorySize, F_SMEM);

    dim3 gb(256);

    // glue
    dim3 gSplit((BSZ * SEQL * DM) / 4 / 256, 3);       // (8192, 3)
    split_qkv_kernel<<<gSplit, gb>>>(q, k, v);
    dim3 tb(32, 8);
    dim3 tg(DM / 32, DM / 32, 4);
    transpose4_kernel<<<tg, tb>>>(Wq, Wk, Wv, Wo);
    pack_mask_kernel<<<(BSZ * SEQL * (SEQL / 32)) / 256, gb>>>(mask);

    // merged Q/K/V projection GEMMs
    dim3 gg(DM / 128, (BSZ * SEQL) / 128, 3);          // (8, 64, 3)
    mma_gemm<0><<<gg, gb, G_SMEM>>>(bq, bk, bv, nullptr);

    // fused attention
    dim3 gF(SEQL / 128, ZTOT);                         // (8, 128)
    flash_mma<<<gF, gb, F_SMEM>>>();

    // output projection
    dim3 go(DM / 128, (BSZ * SEQL) / 128, 1);
    mma_gemm<1><<<go, gb, G_SMEM>>>(bo, nullptr, nullptr, out);
}